// round 2
// baseline (speedup 1.0000x reference)
#include <cuda_runtime.h>
#include <math.h>

#define Hq   4
#define Lq   4096
#define Dq   1024
#define CHK  32
#define NCHK 128
#define MROWS 16384

// ---------------- scratch arena (no cudaMalloc allowed) ----------------
constexpr size_t SZf      = 16777216ull;            // 16384*1024
constexpr size_t OFF_QPRE = 0;                      // reused later as U
constexpr size_t OFF_U    = 0;
constexpr size_t OFF_KPRE = SZf;                    // reused later as W
constexpr size_t OFF_W    = SZf;
constexpr size_t OFF_VPRE = 2*SZf;                  // reused later as DELTA_O
constexpr size_t OFF_DELTA= 2*SZf;
constexpr size_t OFF_Q    = 3*SZf;
constexpr size_t OFF_K    = 4*SZf;
constexpr size_t OFF_V    = 5*SZf;
constexpr size_t OFF_EMAS = 6*SZf;
constexpr size_t OFF_EMAL = 7*SZf;
constexpr size_t OFF_OMIX = 8*SZf;
constexpr size_t OFF_Z    = 9*SZf;                  // 16384*512
constexpr size_t OFF_ATTN = OFF_Z + 8388608ull;     // 2048*1024
constexpr size_t OFF_BETA = OFF_ATTN + 2097152ull;  // 65536
constexpr size_t OFF_GS   = OFF_BETA + 65536ull;
constexpr size_t OFF_GL   = OFF_GS + 65536ull;
constexpr size_t OFF_WGT  = OFF_GL + 65536ull;      // 16384*16
constexpr size_t ARENA_TOTAL = OFF_WGT + 262144ull;

__device__ float g_arena[ARENA_TOTAL];

constexpr int PRE_SMEM_BYTES  = 26816 * 4;   // 107264
constexpr int SCAN_SMEM_BYTES = 36288 * 4;   // 145152

__device__ __forceinline__ float sigm(float x){ return 1.f/(1.f+expf(-x)); }
__device__ __forceinline__ float silu(float x){ return x/(1.f+expf(-x)); }

__device__ __forceinline__ float warp_sum(float v){
    #pragma unroll
    for (int o=16;o>0;o>>=1) v += __shfl_xor_sync(0xffffffffu, v, o);
    return v;
}

// ---------------- generic GEMM: C[M,N] = A[M,K] @ W[N,K]^T (+bias)(+silu) ----
__global__ void gemm_kernel(const float* __restrict__ A, const float* __restrict__ W,
                            const float* __restrict__ bias, float* __restrict__ C,
                            int M, int N, int K, int act)
{
    __shared__ float As[16*65];
    __shared__ float Bs[16*65];
    const int tid = threadIdx.x;
    const int tx = tid & 15, ty = tid >> 4;
    const int m0 = blockIdx.y * 64, n0 = blockIdx.x * 64;
    const int lk = tid & 15, lr = tid >> 4;
    float acc[4][4];
    #pragma unroll
    for (int i=0;i<4;i++)
        #pragma unroll
        for (int j=0;j<4;j++) acc[i][j]=0.f;

    for (int k0=0;k0<K;k0+=16){
        #pragma unroll
        for (int s=0;s<4;s++){
            As[lk*65 + lr + s*16] = A[(size_t)(m0+lr+s*16)*K + k0 + lk];
            Bs[lk*65 + lr + s*16] = W[(size_t)(n0+lr+s*16)*K + k0 + lk];
        }
        __syncthreads();
        #pragma unroll
        for (int kk=0;kk<16;kk++){
            float a[4], b[4];
            #pragma unroll
            for (int i=0;i<4;i++) a[i] = As[kk*65 + ty*4+i];
            #pragma unroll
            for (int j=0;j<4;j++) b[j] = Bs[kk*65 + tx*4+j];
            #pragma unroll
            for (int i=0;i<4;i++)
                #pragma unroll
                for (int j=0;j<4;j++)
                    acc[i][j] = fmaf(a[i], b[j], acc[i][j]);
        }
        __syncthreads();
    }
    #pragma unroll
    for (int i=0;i<4;i++){
        const int m = m0 + ty*4 + i;
        float4 o4;
        float* ov = (float*)&o4;
        #pragma unroll
        for (int j=0;j<4;j++){
            const int n = n0 + tx*4 + j;
            float v = acc[i][j];
            if (bias) v += bias[n];
            if (act==1) v = v / (1.f + expf(-v));
            ov[j] = v;
        }
        *reinterpret_cast<float4*>(&C[(size_t)m*N + n0 + tx*4]) = o4;
    }
}

// ---------------- causal depthwise conv (k=4) + SiLU, relayout to head-major ----
__global__ void conv_silu_kernel(const float* __restrict__ qp, const float* __restrict__ kp,
                                 const float* __restrict__ vp,
                                 const float* __restrict__ wq, const float* __restrict__ wk,
                                 const float* __restrict__ wv,
                                 float* __restrict__ qo, float* __restrict__ ko,
                                 float* __restrict__ vo)
{
    const int row = blockIdx.x;                 // b*L + l
    const int d   = blockIdx.y*256 + threadIdx.x;
    const int l = row & (Lq-1), b = row >> 12;
    const int h = d >> 8, dk = d & 255;
    float aq=0.f, ak=0.f, av=0.f;
    #pragma unroll
    for (int j=0;j<4;j++){
        int ls = l - 3 + j;
        if (ls >= 0){
            size_t idx = (size_t)(row - 3 + j)*Dq + d;
            aq = fmaf(qp[idx], wq[d*4+j], aq);
            ak = fmaf(kp[idx], wk[d*4+j], ak);
            av = fmaf(vp[idx], wv[d*4+j], av);
        }
    }
    size_t o = ((size_t)(b*Hq + h)*Lq + l)*256 + dk;
    qo[o] = silu(aq);
    ko[o] = silu(ak);
    vo[o] = silu(av);
}

// ---------------- beta / g_s / g_l projections ----------------
__global__ void smallproj_kernel(const float* __restrict__ x,
                                 const float* __restrict__ Wb, const float* __restrict__ Wds,
                                 const float* __restrict__ bds, const float* __restrict__ Wdl,
                                 const float* __restrict__ bdl,
                                 float* __restrict__ beta, float* __restrict__ gs,
                                 float* __restrict__ gl)
{
    const int row = blockIdx.x;
    const float* xr = x + (size_t)row*Dq;
    float acc[12];
    #pragma unroll
    for (int r=0;r<12;r++) acc[r]=0.f;
    for (int j=threadIdx.x;j<Dq;j+=256){
        const float xv = xr[j];
        #pragma unroll
        for (int h=0;h<4;h++){
            acc[h]   = fmaf(xv, Wb [h*Dq+j], acc[h]);
            acc[4+h] = fmaf(xv, Wds[h*Dq+j], acc[4+h]);
            acc[8+h] = fmaf(xv, Wdl[h*Dq+j], acc[8+h]);
        }
    }
    __shared__ float red[12][9];
    const int lane = threadIdx.x & 31, w = threadIdx.x >> 5;
    #pragma unroll
    for (int r=0;r<12;r++){
        float s = warp_sum(acc[r]);
        if (lane==0) red[r][w] = s;
    }
    __syncthreads();
    if (threadIdx.x < 12){
        float s = 0.f;
        #pragma unroll
        for (int ww=0;ww<8;ww++) s += red[threadIdx.x][ww];
        const int h = threadIdx.x & 3;
        const int b = row >> 12, l = row & (Lq-1);
        size_t o = (size_t)(b*4 + h)*Lq + l;
        if (threadIdx.x < 4)      beta[o] = sigm(s);
        else if (threadIdx.x < 8) gs[o]   = sigm(s + bds[h]);
        else                      gl[o]   = sigm(s + bdl[h]);
    }
}

// ---------------- delta-rule per-chunk precompute ----------------
// normalizes q,k in place; writes u = Tinv@(v*beta), w = Tinv@(k*beta), attn = tril(q@k^T)
__global__ void chunk_pre_kernel(float* __restrict__ q, float* __restrict__ k,
                                 const float* __restrict__ v, const float* __restrict__ beta,
                                 float* __restrict__ u, float* __restrict__ w,
                                 float* __restrict__ attn)
{
    extern __shared__ float sm[];
    float* qs = sm;              // 32*257
    float* ks = qs + 8224;
    float* vs = ks + 8224;
    float* Lm = vs + 8224;       // 32*33
    float* Ti = Lm + 1056;       // 32*33
    float* bs = Ti + 1056;       // 32
    const int bh = blockIdx.x >> 7;
    const int c  = blockIdx.x & 127;
    const int tid = threadIdx.x, lane = tid&31, wid = tid>>5;
    const size_t base = (size_t)bh*Lq + (size_t)c*CHK;

    for (int idx = tid; idx < 32*256; idx += 256){
        int i = idx >> 8, d = idx & 255;
        size_t g = (base + i)*256 + d;
        qs[i*257+d] = q[g];
        ks[i*257+d] = k[g];
        vs[i*257+d] = v[g];
    }
    if (tid < 32) bs[tid] = beta[base + tid];
    __syncthreads();

    // l2norm rows (warp wid -> rows wid*4 .. wid*4+3)
    #pragma unroll
    for (int r=0;r<4;r++){
        int i = wid*4 + r;
        float sq=0.f, sk=0.f;
        for (int d=lane; d<256; d+=32){
            float a=qs[i*257+d]; sq=fmaf(a,a,sq);
            float bb=ks[i*257+d]; sk=fmaf(bb,bb,sk);
        }
        sq = warp_sum(sq); sk = warp_sum(sk);
        float rq = rsqrtf(sq + 1e-6f), rk = rsqrtf(sk + 1e-6f);
        for (int d=lane; d<256; d+=32){ qs[i*257+d]*=rq; ks[i*257+d]*=rk; }
    }
    __syncthreads();

    // write back normalized q,k; pre-scale v by beta
    for (int idx = tid; idx < 32*256; idx += 256){
        int i = idx>>8, d = idx&255;
        size_t g = (base+i)*256 + d;
        q[g] = qs[i*257+d];
        k[g] = ks[i*257+d];
        vs[i*257+d] *= bs[i];
    }
    __syncthreads();

    // Lm = strict-lower of (k*beta)@k^T ; attn = lower(q@k^T)
    #pragma unroll
    for (int r=0;r<4;r++){
        int i = wid + 8*r;
        float aq=0.f, akk=0.f;
        for (int d=0; d<256; d++){
            float kjd = ks[lane*257+d];
            aq  = fmaf(qs[i*257+d], kjd, aq);
            akk = fmaf(ks[i*257+d], kjd, akk);
        }
        Lm[i*33+lane] = (lane < i) ? bs[i]*akk : 0.f;
        attn[(size_t)blockIdx.x*1024 + i*32 + lane] = (lane <= i) ? aq : 0.f;
    }
    __syncthreads();

    // Tinv = (I + Lm)^{-1} via forward substitution (warp 0, lane = column)
    if (wid == 0){
        for (int i=0;i<32;i++){
            float xv = (lane==i) ? 1.f : 0.f;
            for (int p=0;p<i;p++) xv = fmaf(-Lm[i*33+p], Ti[p*33+lane], xv);
            Ti[i*33+lane] = xv;
            __syncwarp();
        }
    }
    __syncthreads();

    // Tib = Ti * beta[col]  (stored into Lm)
    for (int idx = tid; idx < 1024; idx += 256){
        int i = idx>>5, j = idx&31;
        Lm[i*33+j] = Ti[i*33+j]*bs[j];
    }
    __syncthreads();

    // u = Ti @ (v*beta), w = Tib @ kn
    #pragma unroll
    for (int r=0;r<4;r++){
        int i = wid + 8*r;
        #pragma unroll
        for (int m=0;m<8;m++){
            int d = lane + 32*m;
            float au=0.f, aw=0.f;
            #pragma unroll
            for (int j=0;j<32;j++){
                au = fmaf(Ti[i*33+j], vs[j*257+d], au);
                aw = fmaf(Lm[i*33+j], ks[j*257+d], aw);
            }
            size_t g = (base+i)*256 + d;
            u[g] = au;
            w[g] = aw;
        }
    }
}

// ---------------- delta-rule inter-chunk scan ----------------
// grid: 16 (b,h) * 8 dv-slices of 32. S kept in smem.
__global__ void scan_kernel(const float* __restrict__ q, const float* __restrict__ k,
                            const float* __restrict__ u, const float* __restrict__ w,
                            const float* __restrict__ attn, float* __restrict__ o)
{
    extern __shared__ float sm[];
    float* S   = sm;             // 256*33
    float* ws  = S  + 8448;      // 32*257
    float* ks2 = ws + 8224;
    float* qs2 = ks2+ 8224;
    float* us  = qs2+ 8224;      // 32*33
    float* uh  = us + 1056;      // 32*33
    float* at  = uh + 1056;      // 32*33
    const int bh = blockIdx.x >> 3;
    const int d0 = (blockIdx.x & 7) * 32;
    const int tid = threadIdx.x, lane = tid&31, wid = tid>>5;

    for (int idx = tid; idx < 256*33; idx += 256) S[idx] = 0.f;
    __syncthreads();

    for (int c=0;c<NCHK;c++){
        const size_t base = (size_t)bh*Lq + (size_t)c*32;
        for (int idx = tid; idx < 32*256; idx += 256){
            int i = idx>>8, dk = idx&255;
            size_t g = (base+i)*256 + dk;
            ws[i*257+dk]  = w[g];
            ks2[i*257+dk] = k[g];
            qs2[i*257+dk] = q[g];
        }
        for (int idx = tid; idx < 1024; idx += 256){
            int i = idx>>5, j = idx&31;
            at[i*33+j] = attn[((size_t)bh*NCHK + c)*1024 + idx];
            us[i*33+j] = u[(base+i)*256 + d0 + j];
        }
        __syncthreads();

        // u_hat = u - w @ S   (thread: dd=lane, rows wid*4..wid*4+3)
        {
            float acc[4];
            #pragma unroll
            for (int r=0;r<4;r++) acc[r] = us[(wid*4+r)*33 + lane];
            for (int dk=0;dk<256;dk++){
                float sv = S[dk*33 + lane];
                #pragma unroll
                for (int r=0;r<4;r++) acc[r] = fmaf(-ws[(wid*4+r)*257+dk], sv, acc[r]);
            }
            #pragma unroll
            for (int r=0;r<4;r++) uh[(wid*4+r)*33+lane] = acc[r];
        }
        __syncthreads();

        // o = q @ S + attn @ u_hat  (reads old S)
        {
            float acc[4] = {0.f,0.f,0.f,0.f};
            for (int dk=0;dk<256;dk++){
                float sv = S[dk*33+lane];
                #pragma unroll
                for (int r=0;r<4;r++) acc[r] = fmaf(qs2[(wid*4+r)*257+dk], sv, acc[r]);
            }
            #pragma unroll
            for (int j=0;j<32;j++){
                float uv = uh[j*33+lane];
                #pragma unroll
                for (int r=0;r<4;r++) acc[r] = fmaf(at[(wid*4+r)*33+j], uv, acc[r]);
            }
            #pragma unroll
            for (int r=0;r<4;r++)
                o[(base + wid*4 + r)*256 + d0 + lane] = acc[r];
        }
        __syncthreads();

        // S += k^T @ u_hat  (thread: dd=lane, dk = wid + 8m)
        {
            float uhv[32];
            #pragma unroll
            for (int i=0;i<32;i++) uhv[i] = uh[i*33+lane];
            #pragma unroll 4
            for (int m=0;m<32;m++){
                int dk = wid + 8*m;
                float acc = S[dk*33+lane];
                #pragma unroll
                for (int i=0;i<32;i++) acc = fmaf(ks2[i*257+dk], uhv[i], acc);
                S[dk*33+lane] = acc;
            }
        }
        __syncthreads();
    }
}

// ---------------- dual EMA ----------------
__global__ void ema_kernel(const float* __restrict__ v, const float* __restrict__ gs,
                           const float* __restrict__ gl,
                           float* __restrict__ es, float* __restrict__ el)
{
    const int bh = blockIdx.x;
    const int dv = threadIdx.x;
    const size_t vbase = (size_t)bh*Lq*256 + dv;
    const float* gsp = gs + (size_t)bh*Lq;
    const float* glp = gl + (size_t)bh*Lq;
    float ss = 0.f, sl = 0.f;
    #pragma unroll 8
    for (int t=0;t<Lq;t++){
        float vv = v[vbase + (size_t)t*256];
        float a = gsp[t], b2 = glp[t];
        ss = fmaf(a, ss, (1.f-a)*vv);
        sl = fmaf(b2, sl, (1.f-b2)*vv);
        es[vbase + (size_t)t*256] = ss;
        el[vbase + (size_t)t*256] = sl;
    }
}

// ---------------- hierarchical gate heads ----------------
__global__ void gate_head_kernel(const float* __restrict__ z,
                                 const float* __restrict__ Wc, const float* __restrict__ bc,
                                 const float* __restrict__ Wl, const float* __restrict__ bl,
                                 const float* __restrict__ Wg, const float* __restrict__ bg,
                                 const float* __restrict__ ltc, const float* __restrict__ ltf,
                                 float* __restrict__ wgt)
{
    const int row = blockIdx.x;
    const float* zr = z + (size_t)row*512;
    float acc[24];
    #pragma unroll
    for (int r=0;r<24;r++) acc[r]=0.f;
    for (int j=threadIdx.x;j<512;j+=256){
        float zv = zr[j];
        #pragma unroll
        for (int r=0;r<8;r++){
            acc[r]    = fmaf(zv, Wc[r*512+j], acc[r]);
            acc[8+r]  = fmaf(zv, Wl[r*512+j], acc[8+r]);
            acc[16+r] = fmaf(zv, Wg[r*512+j], acc[16+r]);
        }
    }
    __shared__ float red[24][9];
    const int lane = threadIdx.x&31, w = threadIdx.x>>5;
    #pragma unroll
    for (int r=0;r<24;r++){
        float s = warp_sum(acc[r]);
        if (lane==0) red[r][w] = s;
    }
    __syncthreads();
    if (threadIdx.x < 4){
        const int h = threadIdx.x;
        float sums[6];
        int rs[6] = {2*h, 2*h+1, 8+2*h, 8+2*h+1, 16+2*h, 16+2*h+1};
        #pragma unroll
        for (int t=0;t<6;t++){
            float s=0.f;
            #pragma unroll
            for (int ww=0;ww<8;ww++) s += red[rs[t]][ww];
            sums[t]=s;
        }
        float tc = log1pf(expf(ltc[h])) + 1e-4f;
        float tf = log1pf(expf(ltf[h])) + 1e-4f;
        float c0 = sums[0]+bc[2*h], c1 = sums[1]+bc[2*h+1];
        float l0 = sums[2]+bl[2*h], l1 = sums[3]+bl[2*h+1];
        float g0 = sums[4]+bg[2*h], g1 = sums[5]+bg[2*h+1];
        float pg0 = sigm((c0-c1)/tc), pg1 = 1.f - pg0;
        float q0  = sigm((l0-l1)/tf), q1 = 1.f - q0;
        float r0  = sigm((g0-g1)/tf), r1 = 1.f - r0;
        size_t o = (size_t)row*16 + h*4;
        wgt[o+0] = pg0*q0; wgt[o+1] = pg0*q1; wgt[o+2] = pg1*r0; wgt[o+3] = pg1*r1;
    }
}

// ---------------- mix + per-head RMSNorm ----------------
__global__ void combine_kernel(const float* __restrict__ v, const float* __restrict__ es,
                               const float* __restrict__ el, const float* __restrict__ dl,
                               const float* __restrict__ wgt, const float* __restrict__ onw,
                               float* __restrict__ omix)
{
    const int blk = blockIdx.x;           // row*4 + h
    const int row = blk >> 2, h = blk & 3;
    const int b = row >> 12, l = row & (Lq-1);
    const int tid = threadIdx.x;
    const size_t gbase = ((size_t)(b*4+h)*Lq + l)*256 + tid;
    const float* wp = wgt + (size_t)row*16 + h*4;
    float w0 = wp[0], w1 = wp[1], w2 = wp[2], w3 = wp[3];
    float val = w0*v[gbase] + w1*es[gbase] + w2*dl[gbase] + w3*el[gbase];

    float s = warp_sum(val*val);
    __shared__ float red[8];
    const int lane = tid&31, w = tid>>5;
    if (lane==0) red[w] = s;
    __syncthreads();
    if (w==0){
        float t = (lane<8)?red[lane]:0.f;
        t = warp_sum(t);
        if (lane==0) red[0] = t;
    }
    __syncthreads();
    float rms = rsqrtf(red[0]*(1.f/256.f) + 1e-5f);
    omix[(size_t)row*1024 + h*256 + tid] = val*rms*onw[tid];
}

// ---------------- host ----------------
extern "C" void kernel_launch(void* const* d_in, const int* in_sizes, int n_in,
                              void* d_out, int out_size)
{
    const float* x      = (const float*)d_in[0];
    const float* Wq     = (const float*)d_in[1];
    const float* Wk     = (const float*)d_in[2];
    const float* Wv     = (const float*)d_in[3];
    const float* cqw    = (const float*)d_in[4];
    const float* ckw    = (const float*)d_in[5];
    const float* cvw    = (const float*)d_in[6];
    const float* Wb     = (const float*)d_in[7];
    const float* Wds    = (const float*)d_in[8];
    const float* bds    = (const float*)d_in[9];
    const float* Wdl    = (const float*)d_in[10];
    const float* bdl    = (const float*)d_in[11];
    const float* Wtrunk = (const float*)d_in[12];
    const float* btrunk = (const float*)d_in[13];
    const float* Wcoarse= (const float*)d_in[14];
    const float* bcoarse= (const float*)d_in[15];
    const float* Wlocal = (const float*)d_in[16];
    const float* blocal = (const float*)d_in[17];
    const float* Wglobal= (const float*)d_in[18];
    const float* bglobal= (const float*)d_in[19];
    const float* ltc    = (const float*)d_in[20];
    const float* ltf    = (const float*)d_in[21];
    const float* onw    = (const float*)d_in[22];
    const float* Wo     = (const float*)d_in[23];
    float* out = (float*)d_out;

    float* arena;
    cudaGetSymbolAddress((void**)&arena, g_arena);
    float* qpre = arena + OFF_QPRE;
    float* kpre = arena + OFF_KPRE;
    float* vpre = arena + OFF_VPRE;
    float* qb   = arena + OFF_Q;
    float* kb   = arena + OFF_K;
    float* vb   = arena + OFF_V;
    float* ub   = arena + OFF_U;
    float* wb   = arena + OFF_W;
    float* dlt  = arena + OFF_DELTA;
    float* emas = arena + OFF_EMAS;
    float* emal = arena + OFF_EMAL;
    float* omix = arena + OFF_OMIX;
    float* zb   = arena + OFF_Z;
    float* attn = arena + OFF_ATTN;
    float* beta = arena + OFF_BETA;
    float* gs   = arena + OFF_GS;
    float* gl   = arena + OFF_GL;
    float* wgt  = arena + OFF_WGT;

    cudaFuncSetAttribute(chunk_pre_kernel, cudaFuncAttributeMaxDynamicSharedMemorySize, PRE_SMEM_BYTES);
    cudaFuncSetAttribute(scan_kernel,      cudaFuncAttributeMaxDynamicSharedMemorySize, SCAN_SMEM_BYTES);

    dim3 blk(256);
    dim3 gN(1024/64, MROWS/64);
    dim3 gZ(512/64,  MROWS/64);

    // projections
    gemm_kernel<<<gN, blk>>>(x, Wq, nullptr, qpre, MROWS, 1024, 1024, 0);
    gemm_kernel<<<gN, blk>>>(x, Wk, nullptr, kpre, MROWS, 1024, 1024, 0);
    gemm_kernel<<<gN, blk>>>(x, Wv, nullptr, vpre, MROWS, 1024, 1024, 0);

    // conv + silu + relayout
    conv_silu_kernel<<<dim3(MROWS,4), blk>>>(qpre, kpre, vpre, cqw, ckw, cvw, qb, kb, vb);

    // beta / decays
    smallproj_kernel<<<MROWS, blk>>>(x, Wb, Wds, bds, Wdl, bdl, beta, gs, gl);

    // delta rule
    chunk_pre_kernel<<<2048, blk, PRE_SMEM_BYTES>>>(qb, kb, vb, beta, ub, wb, attn);
    scan_kernel<<<128, blk, SCAN_SMEM_BYTES>>>(qb, kb, ub, wb, attn, dlt);

    // EMAs
    ema_kernel<<<16, blk>>>(vb, gs, gl, emas, emal);

    // gate
    gemm_kernel<<<gZ, blk>>>(x, Wtrunk, btrunk, zb, MROWS, 512, 1024, 1);
    gate_head_kernel<<<MROWS, blk>>>(zb, Wcoarse, bcoarse, Wlocal, blocal,
                                     Wglobal, bglobal, ltc, ltf, wgt);

    // combine + RMSNorm
    combine_kernel<<<MROWS*4, blk>>>(vb, emas, emal, dlt, wgt, onw, omix);

    // output projection
    gemm_kernel<<<gN, blk>>>(omix, Wo, nullptr, out, MROWS, 1024, 1024, 0);
}

// round 3
// speedup vs baseline: 1.3935x; 1.3935x over previous
#include <cuda_runtime.h>
#include <math.h>
#include <mma.h>

using namespace nvcuda;

#define Hq   4
#define Lq   4096
#define Dq   1024
#define CHK  32
#define NCHK 128
#define MROWS 16384

// ---------------- scratch arena (no cudaMalloc allowed) ----------------
constexpr size_t SZf      = 16777216ull;            // 16384*1024
constexpr size_t OFF_QPRE = 0;                      // reused later as U
constexpr size_t OFF_U    = 0;
constexpr size_t OFF_KPRE = SZf;                    // reused later as W
constexpr size_t OFF_W    = SZf;
constexpr size_t OFF_VPRE = 2*SZf;                  // reused later as DELTA_O
constexpr size_t OFF_DELTA= 2*SZf;
constexpr size_t OFF_Q    = 3*SZf;
constexpr size_t OFF_K    = 4*SZf;
constexpr size_t OFF_V    = 5*SZf;
constexpr size_t OFF_EMAS = 6*SZf;
constexpr size_t OFF_EMAL = 7*SZf;
constexpr size_t OFF_OMIX = 8*SZf;
constexpr size_t OFF_Z    = 9*SZf;                  // 16384*512
constexpr size_t OFF_ATTN = OFF_Z + 8388608ull;     // 2048*1024
constexpr size_t OFF_BETA = OFF_ATTN + 2097152ull;  // 65536
constexpr size_t OFF_GS   = OFF_BETA + 65536ull;
constexpr size_t OFF_GL   = OFF_GS + 65536ull;
constexpr size_t OFF_WGT  = OFF_GL + 65536ull;      // 16384*16
constexpr size_t ARENA_TOTAL = OFF_WGT + 262144ull;

__device__ float g_arena[ARENA_TOTAL];

constexpr int PRE_SMEM_BYTES  = 26816 * 4;   // 107264
constexpr int SCAN_SMEM_BYTES = 36288 * 4;   // 145152

__device__ __forceinline__ float sigm(float x){ return 1.f/(1.f+expf(-x)); }
__device__ __forceinline__ float silu(float x){ return x/(1.f+expf(-x)); }

__device__ __forceinline__ float warp_sum(float v){
    #pragma unroll
    for (int o=16;o>0;o>>=1) v += __shfl_xor_sync(0xffffffffu, v, o);
    return v;
}

// ---------------- TF32 tensor-core GEMM: C[M,N] = A[M,K] @ W[N,K]^T ----------
// 64x64 block tile, BK=32, 8 warps (2x4 tile grid, 2 acc frags each).
__global__ void gemm_tf32_kernel(const float* __restrict__ A, const float* __restrict__ W,
                                 const float* __restrict__ bias, float* __restrict__ C,
                                 int M, int N, int K, int act)
{
    __shared__ float smem[2*64*36];
    float* As = smem;             // [64][36]
    float* Ws = smem + 64*36;     // [64][36]
    const int tid = threadIdx.x;
    const int warp = tid >> 5;
    const int m0 = blockIdx.y * 64, n0 = blockIdx.x * 64;
    const int tr = warp >> 1;             // 0..3 : row tile (16 rows)
    const int tc = (warp & 1) * 2;        // 0 or 2 : first of two col tiles

    wmma::fragment<wmma::accumulator,16,16,8,float> acc[2];
    wmma::fill_fragment(acc[0], 0.f);
    wmma::fill_fragment(acc[1], 0.f);

    const int lr = tid >> 3;              // 0..31
    const int lc = (tid & 7) * 4;         // 0,4,...,28

    for (int k0 = 0; k0 < K; k0 += 32){
        #pragma unroll
        for (int s = 0; s < 2; s++){
            int r = lr + s*32;
            *reinterpret_cast<float4*>(&As[r*36 + lc]) =
                *reinterpret_cast<const float4*>(&A[(size_t)(m0+r)*K + k0 + lc]);
            *reinterpret_cast<float4*>(&Ws[r*36 + lc]) =
                *reinterpret_cast<const float4*>(&W[(size_t)(n0+r)*K + k0 + lc]);
        }
        __syncthreads();
        #pragma unroll
        for (int kk = 0; kk < 32; kk += 8){
            wmma::fragment<wmma::matrix_a,16,16,8,wmma::precision::tf32,wmma::row_major> af;
            wmma::load_matrix_sync(af, &As[tr*16*36 + kk], 36);
            #pragma unroll
            for (int t = 0; t < af.num_elements; t++) af.x[t] = wmma::__float_to_tf32(af.x[t]);
            #pragma unroll
            for (int c2 = 0; c2 < 2; c2++){
                wmma::fragment<wmma::matrix_b,16,16,8,wmma::precision::tf32,wmma::col_major> bf;
                wmma::load_matrix_sync(bf, &Ws[(tc+c2)*16*36 + kk], 36);
                #pragma unroll
                for (int t = 0; t < bf.num_elements; t++) bf.x[t] = wmma::__float_to_tf32(bf.x[t]);
                wmma::mma_sync(acc[c2], af, bf, acc[c2]);
            }
        }
        __syncthreads();
    }

    // epilogue via smem (bias / silu)
    float* Cs = smem;   // reuse as [64][72] = 4608 floats
    #pragma unroll
    for (int c2 = 0; c2 < 2; c2++)
        wmma::store_matrix_sync(&Cs[tr*16*72 + (tc+c2)*16], acc[c2], 72, wmma::mem_row_major);
    __syncthreads();

    for (int idx = tid; idx < 1024; idx += 256){
        int row = idx >> 4, col = (idx & 15) * 4;
        float4 v4 = *reinterpret_cast<float4*>(&Cs[row*72 + col]);
        float* vv = (float*)&v4;
        #pragma unroll
        for (int j = 0; j < 4; j++){
            float v = vv[j];
            if (bias) v += bias[n0 + col + j];
            if (act == 1) v = v / (1.f + expf(-v));
            vv[j] = v;
        }
        *reinterpret_cast<float4*>(&C[(size_t)(m0+row)*N + n0 + col]) = v4;
    }
}

// ---------------- causal depthwise conv (k=4) + SiLU, relayout to head-major ----
__global__ void conv_silu_kernel(const float* __restrict__ qp, const float* __restrict__ kp,
                                 const float* __restrict__ vp,
                                 const float* __restrict__ wq, const float* __restrict__ wk,
                                 const float* __restrict__ wv,
                                 float* __restrict__ qo, float* __restrict__ ko,
                                 float* __restrict__ vo)
{
    const int row = blockIdx.x;                 // b*L + l
    const int d   = blockIdx.y*256 + threadIdx.x;
    const int l = row & (Lq-1), b = row >> 12;
    const int h = d >> 8, dk = d & 255;
    float aq=0.f, ak=0.f, av=0.f;
    #pragma unroll
    for (int j=0;j<4;j++){
        int ls = l - 3 + j;
        if (ls >= 0){
            size_t idx = (size_t)(row - 3 + j)*Dq + d;
            aq = fmaf(qp[idx], wq[d*4+j], aq);
            ak = fmaf(kp[idx], wk[d*4+j], ak);
            av = fmaf(vp[idx], wv[d*4+j], av);
        }
    }
    size_t o = ((size_t)(b*Hq + h)*Lq + l)*256 + dk;
    qo[o] = silu(aq);
    ko[o] = silu(ak);
    vo[o] = silu(av);
}

// ---------------- beta / g_s / g_l projections ----------------
__global__ void smallproj_kernel(const float* __restrict__ x,
                                 const float* __restrict__ Wb, const float* __restrict__ Wds,
                                 const float* __restrict__ bds, const float* __restrict__ Wdl,
                                 const float* __restrict__ bdl,
                                 float* __restrict__ beta, float* __restrict__ gs,
                                 float* __restrict__ gl)
{
    const int row = blockIdx.x;
    const float* xr = x + (size_t)row*Dq;
    float acc[12];
    #pragma unroll
    for (int r=0;r<12;r++) acc[r]=0.f;
    for (int j=threadIdx.x;j<Dq;j+=256){
        const float xv = xr[j];
        #pragma unroll
        for (int h=0;h<4;h++){
            acc[h]   = fmaf(xv, Wb [h*Dq+j], acc[h]);
            acc[4+h] = fmaf(xv, Wds[h*Dq+j], acc[4+h]);
            acc[8+h] = fmaf(xv, Wdl[h*Dq+j], acc[8+h]);
        }
    }
    __shared__ float red[12][9];
    const int lane = threadIdx.x & 31, w = threadIdx.x >> 5;
    #pragma unroll
    for (int r=0;r<12;r++){
        float s = warp_sum(acc[r]);
        if (lane==0) red[r][w] = s;
    }
    __syncthreads();
    if (threadIdx.x < 12){
        float s = 0.f;
        #pragma unroll
        for (int ww=0;ww<8;ww++) s += red[threadIdx.x][ww];
        const int h = threadIdx.x & 3;
        const int b = row >> 12, l = row & (Lq-1);
        size_t o = (size_t)(b*4 + h)*Lq + l;
        if (threadIdx.x < 4)      beta[o] = sigm(s);
        else if (threadIdx.x < 8) gs[o]   = sigm(s + bds[h]);
        else                      gl[o]   = sigm(s + bdl[h]);
    }
}

// ---------------- delta-rule per-chunk precompute ----------------
__global__ void chunk_pre_kernel(float* __restrict__ q, float* __restrict__ k,
                                 const float* __restrict__ v, const float* __restrict__ beta,
                                 float* __restrict__ u, float* __restrict__ w,
                                 float* __restrict__ attn)
{
    extern __shared__ float sm[];
    float* qs = sm;              // 32*257
    float* ks = qs + 8224;
    float* vs = ks + 8224;
    float* Lm = vs + 8224;       // 32*33
    float* Ti = Lm + 1056;       // 32*33
    float* bs = Ti + 1056;       // 32
    const int bh = blockIdx.x >> 7;
    const int c  = blockIdx.x & 127;
    const int tid = threadIdx.x, lane = tid&31, wid = tid>>5;
    const size_t base = (size_t)bh*Lq + (size_t)c*CHK;

    for (int idx = tid; idx < 32*256; idx += 256){
        int i = idx >> 8, d = idx & 255;
        size_t g = (base + i)*256 + d;
        qs[i*257+d] = q[g];
        ks[i*257+d] = k[g];
        vs[i*257+d] = v[g];
    }
    if (tid < 32) bs[tid] = beta[base + tid];
    __syncthreads();

    #pragma unroll
    for (int r=0;r<4;r++){
        int i = wid*4 + r;
        float sq=0.f, sk=0.f;
        for (int d=lane; d<256; d+=32){
            float a=qs[i*257+d]; sq=fmaf(a,a,sq);
            float bb=ks[i*257+d]; sk=fmaf(bb,bb,sk);
        }
        sq = warp_sum(sq); sk = warp_sum(sk);
        float rq = rsqrtf(sq + 1e-6f), rk = rsqrtf(sk + 1e-6f);
        for (int d=lane; d<256; d+=32){ qs[i*257+d]*=rq; ks[i*257+d]*=rk; }
    }
    __syncthreads();

    for (int idx = tid; idx < 32*256; idx += 256){
        int i = idx>>8, d = idx&255;
        size_t g = (base+i)*256 + d;
        q[g] = qs[i*257+d];
        k[g] = ks[i*257+d];
        vs[i*257+d] *= bs[i];
    }
    __syncthreads();

    #pragma unroll
    for (int r=0;r<4;r++){
        int i = wid + 8*r;
        float aq=0.f, akk=0.f;
        for (int d=0; d<256; d++){
            float kjd = ks[lane*257+d];
            aq  = fmaf(qs[i*257+d], kjd, aq);
            akk = fmaf(ks[i*257+d], kjd, akk);
        }
        Lm[i*33+lane] = (lane < i) ? bs[i]*akk : 0.f;
        attn[(size_t)blockIdx.x*1024 + i*32 + lane] = (lane <= i) ? aq : 0.f;
    }
    __syncthreads();

    if (wid == 0){
        for (int i=0;i<32;i++){
            float xv = (lane==i) ? 1.f : 0.f;
            for (int p=0;p<i;p++) xv = fmaf(-Lm[i*33+p], Ti[p*33+lane], xv);
            Ti[i*33+lane] = xv;
            __syncwarp();
        }
    }
    __syncthreads();

    for (int idx = tid; idx < 1024; idx += 256){
        int i = idx>>5, j = idx&31;
        Lm[i*33+j] = Ti[i*33+j]*bs[j];
    }
    __syncthreads();

    #pragma unroll
    for (int r=0;r<4;r++){
        int i = wid + 8*r;
        #pragma unroll
        for (int m=0;m<8;m++){
            int d = lane + 32*m;
            float au=0.f, aw=0.f;
            #pragma unroll
            for (int j=0;j<32;j++){
                au = fmaf(Ti[i*33+j], vs[j*257+d], au);
                aw = fmaf(Lm[i*33+j], ks[j*257+d], aw);
            }
            size_t g = (base+i)*256 + d;
            u[g] = au;
            w[g] = aw;
        }
    }
}

// ---------------- delta-rule inter-chunk scan ----------------
__global__ void scan_kernel(const float* __restrict__ q, const float* __restrict__ k,
                            const float* __restrict__ u, const float* __restrict__ w,
                            const float* __restrict__ attn, float* __restrict__ o)
{
    extern __shared__ float sm[];
    float* S   = sm;             // 256*33
    float* ws  = S  + 8448;      // 32*257
    float* ks2 = ws + 8224;
    float* qs2 = ks2+ 8224;
    float* us  = qs2+ 8224;      // 32*33
    float* uh  = us + 1056;      // 32*33
    float* at  = uh + 1056;      // 32*33
    const int bh = blockIdx.x >> 3;
    const int d0 = (blockIdx.x & 7) * 32;
    const int tid = threadIdx.x, lane = tid&31, wid = tid>>5;

    for (int idx = tid; idx < 256*33; idx += 256) S[idx] = 0.f;
    __syncthreads();

    for (int c=0;c<NCHK;c++){
        const size_t base = (size_t)bh*Lq + (size_t)c*32;
        for (int idx = tid; idx < 32*256; idx += 256){
            int i = idx>>8, dk = idx&255;
            size_t g = (base+i)*256 + dk;
            ws[i*257+dk]  = w[g];
            ks2[i*257+dk] = k[g];
            qs2[i*257+dk] = q[g];
        }
        for (int idx = tid; idx < 1024; idx += 256){
            int i = idx>>5, j = idx&31;
            at[i*33+j] = attn[((size_t)bh*NCHK + c)*1024 + idx];
            us[i*33+j] = u[(base+i)*256 + d0 + j];
        }
        __syncthreads();

        {
            float acc[4];
            #pragma unroll
            for (int r=0;r<4;r++) acc[r] = us[(wid*4+r)*33 + lane];
            for (int dk=0;dk<256;dk++){
                float sv = S[dk*33 + lane];
                #pragma unroll
                for (int r=0;r<4;r++) acc[r] = fmaf(-ws[(wid*4+r)*257+dk], sv, acc[r]);
            }
            #pragma unroll
            for (int r=0;r<4;r++) uh[(wid*4+r)*33+lane] = acc[r];
        }
        __syncthreads();

        {
            float acc[4] = {0.f,0.f,0.f,0.f};
            for (int dk=0;dk<256;dk++){
                float sv = S[dk*33+lane];
                #pragma unroll
                for (int r=0;r<4;r++) acc[r] = fmaf(qs2[(wid*4+r)*257+dk], sv, acc[r]);
            }
            #pragma unroll
            for (int j=0;j<32;j++){
                float uv = uh[j*33+lane];
                #pragma unroll
                for (int r=0;r<4;r++) acc[r] = fmaf(at[(wid*4+r)*33+j], uv, acc[r]);
            }
            #pragma unroll
            for (int r=0;r<4;r++)
                o[(base + wid*4 + r)*256 + d0 + lane] = acc[r];
        }
        __syncthreads();

        {
            float uhv[32];
            #pragma unroll
            for (int i=0;i<32;i++) uhv[i] = uh[i*33+lane];
            #pragma unroll 4
            for (int m=0;m<32;m++){
                int dk = wid + 8*m;
                float acc = S[dk*33+lane];
                #pragma unroll
                for (int i=0;i<32;i++) acc = fmaf(ks2[i*257+dk], uhv[i], acc);
                S[dk*33+lane] = acc;
            }
        }
        __syncthreads();
    }
}

// ---------------- dual EMA ----------------
__global__ void ema_kernel(const float* __restrict__ v, const float* __restrict__ gs,
                           const float* __restrict__ gl,
                           float* __restrict__ es, float* __restrict__ el)
{
    const int bh = blockIdx.x;
    const int dv = threadIdx.x;
    const size_t vbase = (size_t)bh*Lq*256 + dv;
    const float* gsp = gs + (size_t)bh*Lq;
    const float* glp = gl + (size_t)bh*Lq;
    float ss = 0.f, sl = 0.f;
    #pragma unroll 8
    for (int t=0;t<Lq;t++){
        float vv = v[vbase + (size_t)t*256];
        float a = gsp[t], b2 = glp[t];
        ss = fmaf(a, ss, (1.f-a)*vv);
        sl = fmaf(b2, sl, (1.f-b2)*vv);
        es[vbase + (size_t)t*256] = ss;
        el[vbase + (size_t)t*256] = sl;
    }
}

// ---------------- hierarchical gate heads ----------------
__global__ void gate_head_kernel(const float* __restrict__ z,
                                 const float* __restrict__ Wc, const float* __restrict__ bc,
                                 const float* __restrict__ Wl, const float* __restrict__ bl,
                                 const float* __restrict__ Wg, const float* __restrict__ bg,
                                 const float* __restrict__ ltc, const float* __restrict__ ltf,
                                 float* __restrict__ wgt)
{
    const int row = blockIdx.x;
    const float* zr = z + (size_t)row*512;
    float acc[24];
    #pragma unroll
    for (int r=0;r<24;r++) acc[r]=0.f;
    for (int j=threadIdx.x;j<512;j+=256){
        float zv = zr[j];
        #pragma unroll
        for (int r=0;r<8;r++){
            acc[r]    = fmaf(zv, Wc[r*512+j], acc[r]);
            acc[8+r]  = fmaf(zv, Wl[r*512+j], acc[8+r]);
            acc[16+r] = fmaf(zv, Wg[r*512+j], acc[16+r]);
        }
    }
    __shared__ float red[24][9];
    const int lane = threadIdx.x&31, w = threadIdx.x>>5;
    #pragma unroll
    for (int r=0;r<24;r++){
        float s = warp_sum(acc[r]);
        if (lane==0) red[r][w] = s;
    }
    __syncthreads();
    if (threadIdx.x < 4){
        const int h = threadIdx.x;
        float sums[6];
        int rs[6] = {2*h, 2*h+1, 8+2*h, 8+2*h+1, 16+2*h, 16+2*h+1};
        #pragma unroll
        for (int t=0;t<6;t++){
            float s=0.f;
            #pragma unroll
            for (int ww=0;ww<8;ww++) s += red[rs[t]][ww];
            sums[t]=s;
        }
        float tc = log1pf(expf(ltc[h])) + 1e-4f;
        float tf = log1pf(expf(ltf[h])) + 1e-4f;
        float c0 = sums[0]+bc[2*h], c1 = sums[1]+bc[2*h+1];
        float l0 = sums[2]+bl[2*h], l1 = sums[3]+bl[2*h+1];
        float g0 = sums[4]+bg[2*h], g1 = sums[5]+bg[2*h+1];
        float pg0 = sigm((c0-c1)/tc), pg1 = 1.f - pg0;
        float q0  = sigm((l0-l1)/tf), q1 = 1.f - q0;
        float r0  = sigm((g0-g1)/tf), r1 = 1.f - r0;
        size_t o = (size_t)row*16 + h*4;
        wgt[o+0] = pg0*q0; wgt[o+1] = pg0*q1; wgt[o+2] = pg1*r0; wgt[o+3] = pg1*r1;
    }
}

// ---------------- mix + per-head RMSNorm ----------------
__global__ void combine_kernel(const float* __restrict__ v, const float* __restrict__ es,
                               const float* __restrict__ el, const float* __restrict__ dl,
                               const float* __restrict__ wgt, const float* __restrict__ onw,
                               float* __restrict__ omix)
{
    const int blk = blockIdx.x;           // row*4 + h
    const int row = blk >> 2, h = blk & 3;
    const int b = row >> 12, l = row & (Lq-1);
    const int tid = threadIdx.x;
    const size_t gbase = ((size_t)(b*4+h)*Lq + l)*256 + tid;
    const float* wp = wgt + (size_t)row*16 + h*4;
    float w0 = wp[0], w1 = wp[1], w2 = wp[2], w3 = wp[3];
    float val = w0*v[gbase] + w1*es[gbase] + w2*dl[gbase] + w3*el[gbase];

    float s = warp_sum(val*val);
    __shared__ float red[8];
    const int lane = tid&31, w = tid>>5;
    if (lane==0) red[w] = s;
    __syncthreads();
    if (w==0){
        float t = (lane<8)?red[lane]:0.f;
        t = warp_sum(t);
        if (lane==0) red[0] = t;
    }
    __syncthreads();
    float rms = rsqrtf(red[0]*(1.f/256.f) + 1e-5f);
    omix[(size_t)row*1024 + h*256 + tid] = val*rms*onw[tid];
}

// ---------------- host ----------------
extern "C" void kernel_launch(void* const* d_in, const int* in_sizes, int n_in,
                              void* d_out, int out_size)
{
    const float* x      = (const float*)d_in[0];
    const float* Wq     = (const float*)d_in[1];
    const float* Wk     = (const float*)d_in[2];
    const float* Wv     = (const float*)d_in[3];
    const float* cqw    = (const float*)d_in[4];
    const float* ckw    = (const float*)d_in[5];
    const float* cvw    = (const float*)d_in[6];
    const float* Wb     = (const float*)d_in[7];
    const float* Wds    = (const float*)d_in[8];
    const float* bds    = (const float*)d_in[9];
    const float* Wdl    = (const float*)d_in[10];
    const float* bdl    = (const float*)d_in[11];
    const float* Wtrunk = (const float*)d_in[12];
    const float* btrunk = (const float*)d_in[13];
    const float* Wcoarse= (const float*)d_in[14];
    const float* bcoarse= (const float*)d_in[15];
    const float* Wlocal = (const float*)d_in[16];
    const float* blocal = (const float*)d_in[17];
    const float* Wglobal= (const float*)d_in[18];
    const float* bglobal= (const float*)d_in[19];
    const float* ltc    = (const float*)d_in[20];
    const float* ltf    = (const float*)d_in[21];
    const float* onw    = (const float*)d_in[22];
    const float* Wo     = (const float*)d_in[23];
    float* out = (float*)d_out;

    float* arena;
    cudaGetSymbolAddress((void**)&arena, g_arena);
    float* qpre = arena + OFF_QPRE;
    float* kpre = arena + OFF_KPRE;
    float* vpre = arena + OFF_VPRE;
    float* qb   = arena + OFF_Q;
    float* kb   = arena + OFF_K;
    float* vb   = arena + OFF_V;
    float* ub   = arena + OFF_U;
    float* wb   = arena + OFF_W;
    float* dlt  = arena + OFF_DELTA;
    float* emas = arena + OFF_EMAS;
    float* emal = arena + OFF_EMAL;
    float* omix = arena + OFF_OMIX;
    float* zb   = arena + OFF_Z;
    float* attn = arena + OFF_ATTN;
    float* beta = arena + OFF_BETA;
    float* gs   = arena + OFF_GS;
    float* gl   = arena + OFF_GL;
    float* wgt  = arena + OFF_WGT;

    cudaFuncSetAttribute(chunk_pre_kernel, cudaFuncAttributeMaxDynamicSharedMemorySize, PRE_SMEM_BYTES);
    cudaFuncSetAttribute(scan_kernel,      cudaFuncAttributeMaxDynamicSharedMemorySize, SCAN_SMEM_BYTES);

    dim3 blk(256);
    dim3 gN(1024/64, MROWS/64);
    dim3 gZ(512/64,  MROWS/64);

    // projections (TF32 tensor cores)
    gemm_tf32_kernel<<<gN, blk>>>(x, Wq, nullptr, qpre, MROWS, 1024, 1024, 0);
    gemm_tf32_kernel<<<gN, blk>>>(x, Wk, nullptr, kpre, MROWS, 1024, 1024, 0);
    gemm_tf32_kernel<<<gN, blk>>>(x, Wv, nullptr, vpre, MROWS, 1024, 1024, 0);

    // conv + silu + relayout
    conv_silu_kernel<<<dim3(MROWS,4), blk>>>(qpre, kpre, vpre, cqw, ckw, cvw, qb, kb, vb);

    // beta / decays
    smallproj_kernel<<<MROWS, blk>>>(x, Wb, Wds, bds, Wdl, bdl, beta, gs, gl);

    // delta rule
    chunk_pre_kernel<<<2048, blk, PRE_SMEM_BYTES>>>(qb, kb, vb, beta, ub, wb, attn);
    scan_kernel<<<128, blk, SCAN_SMEM_BYTES>>>(qb, kb, ub, wb, attn, dlt);

    // EMAs
    ema_kernel<<<16, blk>>>(vb, gs, gl, emas, emal);

    // gate
    gemm_tf32_kernel<<<gZ, blk>>>(x, Wtrunk, btrunk, zb, MROWS, 512, 1024, 1);
    gate_head_kernel<<<MROWS, blk>>>(zb, Wcoarse, bcoarse, Wlocal, blocal,
                                     Wglobal, bglobal, ltc, ltf, wgt);

    // combine + RMSNorm
    combine_kernel<<<MROWS*4, blk>>>(vb, emas, emal, dlt, wgt, onw, omix);

    // output projection
    gemm_tf32_kernel<<<gN, blk>>>(omix, Wo, nullptr, out, MROWS, 1024, 1024, 0);
}

// round 4
// speedup vs baseline: 1.4811x; 1.0628x over previous
#include <cuda_runtime.h>
#include <math.h>
#include <mma.h>

using namespace nvcuda;

#define Hq   4
#define Lq   4096
#define Dq   1024
#define CHK  32
#define NCHK 128
#define MROWS 16384

// ---------------- scratch arena (no cudaMalloc allowed) ----------------
constexpr size_t SZf      = 16777216ull;            // 16384*1024
constexpr size_t OFF_QPRE = 0;                      // reused later as U
constexpr size_t OFF_U    = 0;
constexpr size_t OFF_KPRE = SZf;                    // reused later as W
constexpr size_t OFF_W    = SZf;
constexpr size_t OFF_VPRE = 2*SZf;                  // reused later as DELTA_O
constexpr size_t OFF_DELTA= 2*SZf;
constexpr size_t OFF_Q    = 3*SZf;
constexpr size_t OFF_K    = 4*SZf;
constexpr size_t OFF_V    = 5*SZf;
constexpr size_t OFF_EMAS = 6*SZf;
constexpr size_t OFF_EMAL = 7*SZf;
constexpr size_t OFF_OMIX = 8*SZf;
constexpr size_t OFF_Z    = 9*SZf;                  // 16384*512
constexpr size_t OFF_ATTN = OFF_Z + 8388608ull;     // 2048*1024
constexpr size_t OFF_BETA = OFF_ATTN + 2097152ull;  // 65536
constexpr size_t OFF_GS   = OFF_BETA + 65536ull;
constexpr size_t OFF_GL   = OFF_GS + 65536ull;
constexpr size_t OFF_WGT  = OFF_GL + 65536ull;      // 16384*16
constexpr size_t ARENA_TOTAL = OFF_WGT + 262144ull;

__device__ float g_arena[ARENA_TOTAL];

constexpr int PRE_SMEM_BYTES  = 26816 * 4;   // 107264
constexpr int SCAN_SMEM_BYTES = 36288 * 4;   // 145152

// GEMM tiling
constexpr int GBM = 128, GBN = 64, GBK = 32, GAP = 36;
constexpr int GSTAGE = GBM*GAP + GBN*GAP;    // 6912 floats per stage
constexpr int GEMM_SMEM_BYTES = 2*GSTAGE*4;  // 55296

__device__ __forceinline__ float sigm(float x){ return 1.f/(1.f+expf(-x)); }
__device__ __forceinline__ float silu(float x){ return x/(1.f+expf(-x)); }

__device__ __forceinline__ float warp_sum(float v){
    #pragma unroll
    for (int o=16;o>0;o>>=1) v += __shfl_xor_sync(0xffffffffu, v, o);
    return v;
}

__device__ __forceinline__ void cp16(float* s, const float* g){
    unsigned a = (unsigned)__cvta_generic_to_shared(s);
    asm volatile("cp.async.cg.shared.global [%0], [%1], 16;" :: "r"(a), "l"(g));
}

// ---------------- TF32 tensor-core GEMM: C[M,N] = A[M,K] @ W[N,K]^T ----------
// 128x64 tile, BK=32, double-buffered cp.async, 8 warps each 32x32 (2x2 frags)
__global__ void gemm_tf32_kernel(const float* __restrict__ A, const float* __restrict__ W,
                                 const float* __restrict__ bias, float* __restrict__ C,
                                 int M, int N, int K, int act)
{
    extern __shared__ float smem[];
    const int tid = threadIdx.x, warp = tid>>5;
    const int m0 = blockIdx.y*GBM, n0 = blockIdx.x*GBN;
    const int tr = warp>>1, tcw = warp&1;
    const int lr = tid>>3, lc = (tid&7)*4;

    wmma::fragment<wmma::accumulator,16,16,8,float> acc[2][2];
    #pragma unroll
    for(int i=0;i<2;i++)
        #pragma unroll
        for(int j=0;j<2;j++) wmma::fill_fragment(acc[i][j], 0.f);

    const int KT = K/GBK;

    // prologue load
    {
        float* As = smem;
        float* Ws = As + GBM*GAP;
        #pragma unroll
        for (int s=0;s<4;s++){
            int r = lr + s*32;
            cp16(&As[r*GAP+lc], &A[(size_t)(m0+r)*K + lc]);
        }
        #pragma unroll
        for (int s=0;s<2;s++){
            int r = lr + s*32;
            cp16(&Ws[r*GAP+lc], &W[(size_t)(n0+r)*K + lc]);
        }
        asm volatile("cp.async.commit_group;");
    }

    int buf = 0;
    for (int it=0; it<KT; ++it){
        if (it+1 < KT){
            float* As = smem + (buf^1)*GSTAGE;
            float* Ws = As + GBM*GAP;
            const int k0 = (it+1)*GBK;
            #pragma unroll
            for (int s=0;s<4;s++){
                int r = lr + s*32;
                cp16(&As[r*GAP+lc], &A[(size_t)(m0+r)*K + k0 + lc]);
            }
            #pragma unroll
            for (int s=0;s<2;s++){
                int r = lr + s*32;
                cp16(&Ws[r*GAP+lc], &W[(size_t)(n0+r)*K + k0 + lc]);
            }
            asm volatile("cp.async.commit_group;");
            asm volatile("cp.async.wait_group 1;");
        } else {
            asm volatile("cp.async.wait_group 0;");
        }
        __syncthreads();

        float* As = smem + buf*GSTAGE;
        float* Ws = As + GBM*GAP;
        #pragma unroll
        for (int kk=0; kk<GBK; kk+=8){
            wmma::fragment<wmma::matrix_a,16,16,8,wmma::precision::tf32,wmma::row_major> af[2];
            wmma::fragment<wmma::matrix_b,16,16,8,wmma::precision::tf32,wmma::col_major> bf[2];
            #pragma unroll
            for (int i=0;i<2;i++){
                wmma::load_matrix_sync(af[i], &As[(tr*32+i*16)*GAP + kk], GAP);
                #pragma unroll
                for (int t=0;t<af[i].num_elements;t++) af[i].x[t] = wmma::__float_to_tf32(af[i].x[t]);
            }
            #pragma unroll
            for (int j=0;j<2;j++){
                wmma::load_matrix_sync(bf[j], &Ws[(tcw*32+j*16)*GAP + kk], GAP);
                #pragma unroll
                for (int t=0;t<bf[j].num_elements;t++) bf[j].x[t] = wmma::__float_to_tf32(bf[j].x[t]);
            }
            #pragma unroll
            for (int i=0;i<2;i++)
                #pragma unroll
                for (int j=0;j<2;j++)
                    wmma::mma_sync(acc[i][j], af[i], bf[j], acc[i][j]);
        }
        __syncthreads();
        buf ^= 1;
    }

    // epilogue via smem (bias / silu)
    float* Cs = smem;   // [128][72]
    #pragma unroll
    for (int i=0;i<2;i++)
        #pragma unroll
        for (int j=0;j<2;j++)
            wmma::store_matrix_sync(&Cs[(tr*32+i*16)*72 + tcw*32 + j*16], acc[i][j], 72, wmma::mem_row_major);
    __syncthreads();

    for (int idx = tid; idx < GBM*GBN/4; idx += 256){
        int row = idx >> 4, col = (idx & 15)*4;
        float4 v4 = *reinterpret_cast<float4*>(&Cs[row*72 + col]);
        float* vv = (float*)&v4;
        #pragma unroll
        for (int j=0;j<4;j++){
            float v = vv[j];
            if (bias) v += bias[n0+col+j];
            if (act==1) v = v/(1.f+expf(-v));
            vv[j] = v;
        }
        *reinterpret_cast<float4*>(&C[(size_t)(m0+row)*N + n0+col]) = v4;
    }
}

// ---------------- causal depthwise conv (k=4) + SiLU, relayout to head-major ----
__global__ void conv_silu_kernel(const float* __restrict__ qp, const float* __restrict__ kp,
                                 const float* __restrict__ vp,
                                 const float* __restrict__ wq, const float* __restrict__ wk,
                                 const float* __restrict__ wv,
                                 float* __restrict__ qo, float* __restrict__ ko,
                                 float* __restrict__ vo)
{
    const int row = blockIdx.x;                 // b*L + l
    const int d   = blockIdx.y*256 + threadIdx.x;
    const int l = row & (Lq-1), b = row >> 12;
    const int h = d >> 8, dk = d & 255;
    float aq=0.f, ak=0.f, av=0.f;
    #pragma unroll
    for (int j=0;j<4;j++){
        int ls = l - 3 + j;
        if (ls >= 0){
            size_t idx = (size_t)(row - 3 + j)*Dq + d;
            aq = fmaf(qp[idx], wq[d*4+j], aq);
            ak = fmaf(kp[idx], wk[d*4+j], ak);
            av = fmaf(vp[idx], wv[d*4+j], av);
        }
    }
    size_t o = ((size_t)(b*Hq + h)*Lq + l)*256 + dk;
    qo[o] = silu(aq);
    ko[o] = silu(ak);
    vo[o] = silu(av);
}

// ---------------- beta / g_s / g_l projections ----------------
__global__ void smallproj_kernel(const float* __restrict__ x,
                                 const float* __restrict__ Wb, const float* __restrict__ Wds,
                                 const float* __restrict__ bds, const float* __restrict__ Wdl,
                                 const float* __restrict__ bdl,
                                 float* __restrict__ beta, float* __restrict__ gs,
                                 float* __restrict__ gl)
{
    const int row = blockIdx.x;
    const float* xr = x + (size_t)row*Dq;
    float acc[12];
    #pragma unroll
    for (int r=0;r<12;r++) acc[r]=0.f;
    for (int j=threadIdx.x;j<Dq;j+=256){
        const float xv = xr[j];
        #pragma unroll
        for (int h=0;h<4;h++){
            acc[h]   = fmaf(xv, Wb [h*Dq+j], acc[h]);
            acc[4+h] = fmaf(xv, Wds[h*Dq+j], acc[4+h]);
            acc[8+h] = fmaf(xv, Wdl[h*Dq+j], acc[8+h]);
        }
    }
    __shared__ float red[12][9];
    const int lane = threadIdx.x & 31, w = threadIdx.x >> 5;
    #pragma unroll
    for (int r=0;r<12;r++){
        float s = warp_sum(acc[r]);
        if (lane==0) red[r][w] = s;
    }
    __syncthreads();
    if (threadIdx.x < 12){
        float s = 0.f;
        #pragma unroll
        for (int ww=0;ww<8;ww++) s += red[threadIdx.x][ww];
        const int h = threadIdx.x & 3;
        const int b = row >> 12, l = row & (Lq-1);
        size_t o = (size_t)(b*4 + h)*Lq + l;
        if (threadIdx.x < 4)      beta[o] = sigm(s);
        else if (threadIdx.x < 8) gs[o]   = sigm(s + bds[h]);
        else                      gl[o]   = sigm(s + bdl[h]);
    }
}

// ---------------- delta-rule per-chunk precompute ----------------
__global__ void chunk_pre_kernel(float* __restrict__ q, float* __restrict__ k,
                                 const float* __restrict__ v, const float* __restrict__ beta,
                                 float* __restrict__ u, float* __restrict__ w,
                                 float* __restrict__ attn)
{
    extern __shared__ float sm[];
    float* qs = sm;              // 32*257
    float* ks = qs + 8224;
    float* vs = ks + 8224;
    float* Lm = vs + 8224;       // 32*33
    float* Ti = Lm + 1056;       // 32*33
    float* bs = Ti + 1056;       // 32
    const int bh = blockIdx.x >> 7;
    const int c  = blockIdx.x & 127;
    const int tid = threadIdx.x, lane = tid&31, wid = tid>>5;
    const size_t base = (size_t)bh*Lq + (size_t)c*CHK;

    for (int idx = tid; idx < 32*256; idx += 256){
        int i = idx >> 8, d = idx & 255;
        size_t g = (base + i)*256 + d;
        qs[i*257+d] = q[g];
        ks[i*257+d] = k[g];
        vs[i*257+d] = v[g];
    }
    if (tid < 32) bs[tid] = beta[base + tid];
    __syncthreads();

    #pragma unroll
    for (int r=0;r<4;r++){
        int i = wid*4 + r;
        float sq=0.f, sk=0.f;
        for (int d=lane; d<256; d+=32){
            float a=qs[i*257+d]; sq=fmaf(a,a,sq);
            float bb=ks[i*257+d]; sk=fmaf(bb,bb,sk);
        }
        sq = warp_sum(sq); sk = warp_sum(sk);
        float rq = rsqrtf(sq + 1e-6f), rk = rsqrtf(sk + 1e-6f);
        for (int d=lane; d<256; d+=32){ qs[i*257+d]*=rq; ks[i*257+d]*=rk; }
    }
    __syncthreads();

    for (int idx = tid; idx < 32*256; idx += 256){
        int i = idx>>8, d = idx&255;
        size_t g = (base+i)*256 + d;
        q[g] = qs[i*257+d];
        k[g] = ks[i*257+d];
        vs[i*257+d] *= bs[i];
    }
    __syncthreads();

    #pragma unroll
    for (int r=0;r<4;r++){
        int i = wid + 8*r;
        float aq=0.f, akk=0.f;
        for (int d=0; d<256; d++){
            float kjd = ks[lane*257+d];
            aq  = fmaf(qs[i*257+d], kjd, aq);
            akk = fmaf(ks[i*257+d], kjd, akk);
        }
        Lm[i*33+lane] = (lane < i) ? bs[i]*akk : 0.f;
        attn[(size_t)blockIdx.x*1024 + i*32 + lane] = (lane <= i) ? aq : 0.f;
    }
    __syncthreads();

    if (wid == 0){
        for (int i=0;i<32;i++){
            float xv = (lane==i) ? 1.f : 0.f;
            for (int p=0;p<i;p++) xv = fmaf(-Lm[i*33+p], Ti[p*33+lane], xv);
            Ti[i*33+lane] = xv;
            __syncwarp();
        }
    }
    __syncthreads();

    for (int idx = tid; idx < 1024; idx += 256){
        int i = idx>>5, j = idx&31;
        Lm[i*33+j] = Ti[i*33+j]*bs[j];
    }
    __syncthreads();

    #pragma unroll
    for (int r=0;r<4;r++){
        int i = wid + 8*r;
        #pragma unroll
        for (int m=0;m<8;m++){
            int d = lane + 32*m;
            float au=0.f, aw=0.f;
            #pragma unroll
            for (int j=0;j<32;j++){
                au = fmaf(Ti[i*33+j], vs[j*257+d], au);
                aw = fmaf(Lm[i*33+j], ks[j*257+d], aw);
            }
            size_t g = (base+i)*256 + d;
            u[g] = au;
            w[g] = aw;
        }
    }
}

// ---------------- delta-rule inter-chunk scan ----------------
__global__ void scan_kernel(const float* __restrict__ q, const float* __restrict__ k,
                            const float* __restrict__ u, const float* __restrict__ w,
                            const float* __restrict__ attn, float* __restrict__ o)
{
    extern __shared__ float sm[];
    float* S   = sm;             // 256*33
    float* ws  = S  + 8448;      // 32*257
    float* ks2 = ws + 8224;
    float* qs2 = ks2+ 8224;
    float* us  = qs2+ 8224;      // 32*33
    float* uh  = us + 1056;      // 32*33
    float* at  = uh + 1056;      // 32*33
    const int bh = blockIdx.x >> 3;
    const int d0 = (blockIdx.x & 7) * 32;
    const int tid = threadIdx.x, lane = tid&31, wid = tid>>5;

    for (int idx = tid; idx < 256*33; idx += 256) S[idx] = 0.f;
    __syncthreads();

    for (int c=0;c<NCHK;c++){
        const size_t base = (size_t)bh*Lq + (size_t)c*32;
        for (int idx = tid; idx < 32*256; idx += 256){
            int i = idx>>8, dk = idx&255;
            size_t g = (base+i)*256 + dk;
            ws[i*257+dk]  = w[g];
            ks2[i*257+dk] = k[g];
            qs2[i*257+dk] = q[g];
        }
        for (int idx = tid; idx < 1024; idx += 256){
            int i = idx>>5, j = idx&31;
            at[i*33+j] = attn[((size_t)bh*NCHK + c)*1024 + idx];
            us[i*33+j] = u[(base+i)*256 + d0 + j];
        }
        __syncthreads();

        {
            float acc[4];
            #pragma unroll
            for (int r=0;r<4;r++) acc[r] = us[(wid*4+r)*33 + lane];
            for (int dk=0;dk<256;dk++){
                float sv = S[dk*33 + lane];
                #pragma unroll
                for (int r=0;r<4;r++) acc[r] = fmaf(-ws[(wid*4+r)*257+dk], sv, acc[r]);
            }
            #pragma unroll
            for (int r=0;r<4;r++) uh[(wid*4+r)*33+lane] = acc[r];
        }
        __syncthreads();

        {
            float acc[4] = {0.f,0.f,0.f,0.f};
            for (int dk=0;dk<256;dk++){
                float sv = S[dk*33+lane];
                #pragma unroll
                for (int r=0;r<4;r++) acc[r] = fmaf(qs2[(wid*4+r)*257+dk], sv, acc[r]);
            }
            #pragma unroll
            for (int j=0;j<32;j++){
                float uv = uh[j*33+lane];
                #pragma unroll
                for (int r=0;r<4;r++) acc[r] = fmaf(at[(wid*4+r)*33+j], uv, acc[r]);
            }
            #pragma unroll
            for (int r=0;r<4;r++)
                o[(base + wid*4 + r)*256 + d0 + lane] = acc[r];
        }
        __syncthreads();

        {
            float uhv[32];
            #pragma unroll
            for (int i=0;i<32;i++) uhv[i] = uh[i*33+lane];
            #pragma unroll 4
            for (int m=0;m<32;m++){
                int dk = wid + 8*m;
                float acc = S[dk*33+lane];
                #pragma unroll
                for (int i=0;i<32;i++) acc = fmaf(ks2[i*257+dk], uhv[i], acc);
                S[dk*33+lane] = acc;
            }
        }
        __syncthreads();
    }
}

// ---------------- dual EMA (128 blocks x 32 threads) ----------------
__global__ void ema_kernel(const float* __restrict__ v, const float* __restrict__ gs,
                           const float* __restrict__ gl,
                           float* __restrict__ es, float* __restrict__ el)
{
    const int bh = blockIdx.x >> 3;
    const int dv = ((blockIdx.x & 7) << 5) + threadIdx.x;
    const size_t vbase = (size_t)bh*Lq*256 + dv;
    const float* gsp = gs + (size_t)bh*Lq;
    const float* glp = gl + (size_t)bh*Lq;
    float ss = 0.f, sl = 0.f;
    #pragma unroll 8
    for (int t=0;t<Lq;t++){
        float vv = v[vbase + (size_t)t*256];
        float a = gsp[t], b2 = glp[t];
        ss = fmaf(a, ss, (1.f-a)*vv);
        sl = fmaf(b2, sl, (1.f-b2)*vv);
        es[vbase + (size_t)t*256] = ss;
        el[vbase + (size_t)t*256] = sl;
    }
}

// ---------------- hierarchical gate heads ----------------
__global__ void gate_head_kernel(const float* __restrict__ z,
                                 const float* __restrict__ Wc, const float* __restrict__ bc,
                                 const float* __restrict__ Wl, const float* __restrict__ bl,
                                 const float* __restrict__ Wg, const float* __restrict__ bg,
                                 const float* __restrict__ ltc, const float* __restrict__ ltf,
                                 float* __restrict__ wgt)
{
    const int row = blockIdx.x;
    const float* zr = z + (size_t)row*512;
    float acc[24];
    #pragma unroll
    for (int r=0;r<24;r++) acc[r]=0.f;
    for (int j=threadIdx.x;j<512;j+=256){
        float zv = zr[j];
        #pragma unroll
        for (int r=0;r<8;r++){
            acc[r]    = fmaf(zv, Wc[r*512+j], acc[r]);
            acc[8+r]  = fmaf(zv, Wl[r*512+j], acc[8+r]);
            acc[16+r] = fmaf(zv, Wg[r*512+j], acc[16+r]);
        }
    }
    __shared__ float red[24][9];
    const int lane = threadIdx.x&31, w = threadIdx.x>>5;
    #pragma unroll
    for (int r=0;r<24;r++){
        float s = warp_sum(acc[r]);
        if (lane==0) red[r][w] = s;
    }
    __syncthreads();
    if (threadIdx.x < 4){
        const int h = threadIdx.x;
        float sums[6];
        int rs[6] = {2*h, 2*h+1, 8+2*h, 8+2*h+1, 16+2*h, 16+2*h+1};
        #pragma unroll
        for (int t=0;t<6;t++){
            float s=0.f;
            #pragma unroll
            for (int ww=0;ww<8;ww++) s += red[rs[t]][ww];
            sums[t]=s;
        }
        float tc = log1pf(expf(ltc[h])) + 1e-4f;
        float tf = log1pf(expf(ltf[h])) + 1e-4f;
        float c0 = sums[0]+bc[2*h], c1 = sums[1]+bc[2*h+1];
        float l0 = sums[2]+bl[2*h], l1 = sums[3]+bl[2*h+1];
        float g0 = sums[4]+bg[2*h], g1 = sums[5]+bg[2*h+1];
        float pg0 = sigm((c0-c1)/tc), pg1 = 1.f - pg0;
        float q0  = sigm((l0-l1)/tf), q1 = 1.f - q0;
        float r0  = sigm((g0-g1)/tf), r1 = 1.f - r0;
        size_t o = (size_t)row*16 + h*4;
        wgt[o+0] = pg0*q0; wgt[o+1] = pg0*q1; wgt[o+2] = pg1*r0; wgt[o+3] = pg1*r1;
    }
}

// ---------------- mix + per-head RMSNorm ----------------
__global__ void combine_kernel(const float* __restrict__ v, const float* __restrict__ es,
                               const float* __restrict__ el, const float* __restrict__ dl,
                               const float* __restrict__ wgt, const float* __restrict__ onw,
                               float* __restrict__ omix)
{
    const int blk = blockIdx.x;           // row*4 + h
    const int row = blk >> 2, h = blk & 3;
    const int b = row >> 12, l = row & (Lq-1);
    const int tid = threadIdx.x;
    const size_t gbase = ((size_t)(b*4+h)*Lq + l)*256 + tid;
    const float* wp = wgt + (size_t)row*16 + h*4;
    float w0 = wp[0], w1 = wp[1], w2 = wp[2], w3 = wp[3];
    float val = w0*v[gbase] + w1*es[gbase] + w2*dl[gbase] + w3*el[gbase];

    float s = warp_sum(val*val);
    __shared__ float red[8];
    const int lane = tid&31, w = tid>>5;
    if (lane==0) red[w] = s;
    __syncthreads();
    if (w==0){
        float t = (lane<8)?red[lane]:0.f;
        t = warp_sum(t);
        if (lane==0) red[0] = t;
    }
    __syncthreads();
    float rms = rsqrtf(red[0]*(1.f/256.f) + 1e-5f);
    omix[(size_t)row*1024 + h*256 + tid] = val*rms*onw[tid];
}

// ---------------- host ----------------
extern "C" void kernel_launch(void* const* d_in, const int* in_sizes, int n_in,
                              void* d_out, int out_size)
{
    const float* x      = (const float*)d_in[0];
    const float* Wq     = (const float*)d_in[1];
    const float* Wk     = (const float*)d_in[2];
    const float* Wv     = (const float*)d_in[3];
    const float* cqw    = (const float*)d_in[4];
    const float* ckw    = (const float*)d_in[5];
    const float* cvw    = (const float*)d_in[6];
    const float* Wb     = (const float*)d_in[7];
    const float* Wds    = (const float*)d_in[8];
    const float* bds    = (const float*)d_in[9];
    const float* Wdl    = (const float*)d_in[10];
    const float* bdl    = (const float*)d_in[11];
    const float* Wtrunk = (const float*)d_in[12];
    const float* btrunk = (const float*)d_in[13];
    const float* Wcoarse= (const float*)d_in[14];
    const float* bcoarse= (const float*)d_in[15];
    const float* Wlocal = (const float*)d_in[16];
    const float* blocal = (const float*)d_in[17];
    const float* Wglobal= (const float*)d_in[18];
    const float* bglobal= (const float*)d_in[19];
    const float* ltc    = (const float*)d_in[20];
    const float* ltf    = (const float*)d_in[21];
    const float* onw    = (const float*)d_in[22];
    const float* Wo     = (const float*)d_in[23];
    float* out = (float*)d_out;

    float* arena;
    cudaGetSymbolAddress((void**)&arena, g_arena);
    float* qpre = arena + OFF_QPRE;
    float* kpre = arena + OFF_KPRE;
    float* vpre = arena + OFF_VPRE;
    float* qb   = arena + OFF_Q;
    float* kb   = arena + OFF_K;
    float* vb   = arena + OFF_V;
    float* ub   = arena + OFF_U;
    float* wb   = arena + OFF_W;
    float* dlt  = arena + OFF_DELTA;
    float* emas = arena + OFF_EMAS;
    float* emal = arena + OFF_EMAL;
    float* omix = arena + OFF_OMIX;
    float* zb   = arena + OFF_Z;
    float* attn = arena + OFF_ATTN;
    float* beta = arena + OFF_BETA;
    float* gs   = arena + OFF_GS;
    float* gl   = arena + OFF_GL;
    float* wgt  = arena + OFF_WGT;

    cudaFuncSetAttribute(gemm_tf32_kernel, cudaFuncAttributeMaxDynamicSharedMemorySize, GEMM_SMEM_BYTES);
    cudaFuncSetAttribute(chunk_pre_kernel, cudaFuncAttributeMaxDynamicSharedMemorySize, PRE_SMEM_BYTES);
    cudaFuncSetAttribute(scan_kernel,      cudaFuncAttributeMaxDynamicSharedMemorySize, SCAN_SMEM_BYTES);

    dim3 blk(256);
    dim3 gN(1024/GBN, MROWS/GBM);
    dim3 gZ(512/GBN,  MROWS/GBM);

    // projections (TF32 tensor cores, double-buffered)
    gemm_tf32_kernel<<<gN, blk, GEMM_SMEM_BYTES>>>(x, Wq, nullptr, qpre, MROWS, 1024, 1024, 0);
    gemm_tf32_kernel<<<gN, blk, GEMM_SMEM_BYTES>>>(x, Wk, nullptr, kpre, MROWS, 1024, 1024, 0);
    gemm_tf32_kernel<<<gN, blk, GEMM_SMEM_BYTES>>>(x, Wv, nullptr, vpre, MROWS, 1024, 1024, 0);

    // conv + silu + relayout
    conv_silu_kernel<<<dim3(MROWS,4), blk>>>(qpre, kpre, vpre, cqw, ckw, cvw, qb, kb, vb);

    // beta / decays
    smallproj_kernel<<<MROWS, blk>>>(x, Wb, Wds, bds, Wdl, bdl, beta, gs, gl);

    // delta rule
    chunk_pre_kernel<<<2048, blk, PRE_SMEM_BYTES>>>(qb, kb, vb, beta, ub, wb, attn);
    scan_kernel<<<128, blk, SCAN_SMEM_BYTES>>>(qb, kb, ub, wb, attn, dlt);

    // EMAs
    ema_kernel<<<128, 32>>>(vb, gs, gl, emas, emal);

    // gate
    gemm_tf32_kernel<<<gZ, blk, GEMM_SMEM_BYTES>>>(x, Wtrunk, btrunk, zb, MROWS, 512, 1024, 1);
    gate_head_kernel<<<MROWS, blk>>>(zb, Wcoarse, bcoarse, Wlocal, blocal,
                                     Wglobal, bglobal, ltc, ltf, wgt);

    // combine + RMSNorm
    combine_kernel<<<MROWS*4, blk>>>(vb, emas, emal, dlt, wgt, onw, omix);

    // output projection
    gemm_tf32_kernel<<<gN, blk, GEMM_SMEM_BYTES>>>(omix, Wo, nullptr, out, MROWS, 1024, 1024, 0);
}

// round 5
// speedup vs baseline: 1.6462x; 1.1115x over previous
#include <cuda_runtime.h>
#include <math.h>
#include <mma.h>

using namespace nvcuda;

#define Hq   4
#define Lq   4096
#define Dq   1024
#define CHK  32
#define NCHK 128
#define MROWS 16384

// ---------------- scratch arena (no cudaMalloc allowed) ----------------
constexpr size_t SZf      = 16777216ull;            // 16384*1024
constexpr size_t OFF_QPRE = 0;                      // reused later as U
constexpr size_t OFF_U    = 0;
constexpr size_t OFF_KPRE = SZf;                    // reused later as W
constexpr size_t OFF_W    = SZf;
constexpr size_t OFF_VPRE = 2*SZf;                  // reused later as DELTA_O
constexpr size_t OFF_DELTA= 2*SZf;
constexpr size_t OFF_Q    = 3*SZf;
constexpr size_t OFF_K    = 4*SZf;
constexpr size_t OFF_V    = 5*SZf;
constexpr size_t OFF_EMAS = 6*SZf;
constexpr size_t OFF_EMAL = 7*SZf;
constexpr size_t OFF_OMIX = 8*SZf;
constexpr size_t OFF_Z    = 9*SZf;                  // 16384*512
constexpr size_t OFF_ATTN = OFF_Z + 8388608ull;     // 2048*1024
constexpr size_t OFF_BETA = OFF_ATTN + 2097152ull;  // 65536
constexpr size_t OFF_GS   = OFF_BETA + 65536ull;
constexpr size_t OFF_GL   = OFF_GS + 65536ull;
constexpr size_t OFF_WGT  = OFF_GL + 65536ull;      // 16384*16
constexpr size_t ARENA_TOTAL = OFF_WGT + 262144ull;

__device__ float g_arena[ARENA_TOTAL];

constexpr int PRE_SMEM_BYTES  = 26816 * 4;   // 107264

// wmma scan smem: S, Shi, Slo (256x36) + uh, uhh, uhl (32x36)
constexpr int SLD = 36;
constexpr int SCAN_SMEM_FLOATS = 3*256*SLD + 3*32*SLD;  // 31104
constexpr int SCAN_SMEM_BYTES  = SCAN_SMEM_FLOATS * 4;  // 124416

// GEMM tiling
constexpr int GBM = 128, GBN = 64, GBK = 32, GAP = 36;
constexpr int GSTAGE = GBM*GAP + GBN*GAP;    // 6912 floats per stage
constexpr int GEMM_SMEM_BYTES = 2*GSTAGE*4;  // 55296

__device__ __forceinline__ float sigm(float x){ return 1.f/(1.f+expf(-x)); }
__device__ __forceinline__ float silu(float x){ return x/(1.f+expf(-x)); }

__device__ __forceinline__ float warp_sum(float v){
    #pragma unroll
    for (int o=16;o>0;o>>=1) v += __shfl_xor_sync(0xffffffffu, v, o);
    return v;
}

__device__ __forceinline__ void cp16(float* s, const float* g){
    unsigned a = (unsigned)__cvta_generic_to_shared(s);
    asm volatile("cp.async.cg.shared.global [%0], [%1], 16;" :: "r"(a), "l"(g));
}

// ---------------- TF32 tensor-core GEMM: C[M,N] = A[M,K] @ W[N,K]^T ----------
__global__ void gemm_tf32_kernel(const float* __restrict__ A, const float* __restrict__ W,
                                 const float* __restrict__ bias, float* __restrict__ C,
                                 int M, int N, int K, int act)
{
    extern __shared__ float smem[];
    const int tid = threadIdx.x, warp = tid>>5;
    const int m0 = blockIdx.y*GBM, n0 = blockIdx.x*GBN;
    const int tr = warp>>1, tcw = warp&1;
    const int lr = tid>>3, lc = (tid&7)*4;

    wmma::fragment<wmma::accumulator,16,16,8,float> acc[2][2];
    #pragma unroll
    for(int i=0;i<2;i++)
        #pragma unroll
        for(int j=0;j<2;j++) wmma::fill_fragment(acc[i][j], 0.f);

    const int KT = K/GBK;

    {
        float* As = smem;
        float* Ws = As + GBM*GAP;
        #pragma unroll
        for (int s=0;s<4;s++){
            int r = lr + s*32;
            cp16(&As[r*GAP+lc], &A[(size_t)(m0+r)*K + lc]);
        }
        #pragma unroll
        for (int s=0;s<2;s++){
            int r = lr + s*32;
            cp16(&Ws[r*GAP+lc], &W[(size_t)(n0+r)*K + lc]);
        }
        asm volatile("cp.async.commit_group;");
    }

    int buf = 0;
    for (int it=0; it<KT; ++it){
        if (it+1 < KT){
            float* As = smem + (buf^1)*GSTAGE;
            float* Ws = As + GBM*GAP;
            const int k0 = (it+1)*GBK;
            #pragma unroll
            for (int s=0;s<4;s++){
                int r = lr + s*32;
                cp16(&As[r*GAP+lc], &A[(size_t)(m0+r)*K + k0 + lc]);
            }
            #pragma unroll
            for (int s=0;s<2;s++){
                int r = lr + s*32;
                cp16(&Ws[r*GAP+lc], &W[(size_t)(n0+r)*K + k0 + lc]);
            }
            asm volatile("cp.async.commit_group;");
            asm volatile("cp.async.wait_group 1;");
        } else {
            asm volatile("cp.async.wait_group 0;");
        }
        __syncthreads();

        float* As = smem + buf*GSTAGE;
        float* Ws = As + GBM*GAP;
        #pragma unroll
        for (int kk=0; kk<GBK; kk+=8){
            wmma::fragment<wmma::matrix_a,16,16,8,wmma::precision::tf32,wmma::row_major> af[2];
            wmma::fragment<wmma::matrix_b,16,16,8,wmma::precision::tf32,wmma::col_major> bf[2];
            #pragma unroll
            for (int i=0;i<2;i++){
                wmma::load_matrix_sync(af[i], &As[(tr*32+i*16)*GAP + kk], GAP);
                #pragma unroll
                for (int t=0;t<af[i].num_elements;t++) af[i].x[t] = wmma::__float_to_tf32(af[i].x[t]);
            }
            #pragma unroll
            for (int j=0;j<2;j++){
                wmma::load_matrix_sync(bf[j], &Ws[(tcw*32+j*16)*GAP + kk], GAP);
                #pragma unroll
                for (int t=0;t<bf[j].num_elements;t++) bf[j].x[t] = wmma::__float_to_tf32(bf[j].x[t]);
            }
            #pragma unroll
            for (int i=0;i<2;i++)
                #pragma unroll
                for (int j=0;j<2;j++)
                    wmma::mma_sync(acc[i][j], af[i], bf[j], acc[i][j]);
        }
        __syncthreads();
        buf ^= 1;
    }

    float* Cs = smem;   // [128][72]
    #pragma unroll
    for (int i=0;i<2;i++)
        #pragma unroll
        for (int j=0;j<2;j++)
            wmma::store_matrix_sync(&Cs[(tr*32+i*16)*72 + tcw*32 + j*16], acc[i][j], 72, wmma::mem_row_major);
    __syncthreads();

    for (int idx = tid; idx < GBM*GBN/4; idx += 256){
        int row = idx >> 4, col = (idx & 15)*4;
        float4 v4 = *reinterpret_cast<float4*>(&Cs[row*72 + col]);
        float* vv = (float*)&v4;
        #pragma unroll
        for (int j=0;j<4;j++){
            float v = vv[j];
            if (bias) v += bias[n0+col+j];
            if (act==1) v = v/(1.f+expf(-v));
            vv[j] = v;
        }
        *reinterpret_cast<float4*>(&C[(size_t)(m0+row)*N + n0+col]) = v4;
    }
}

// ---------------- causal depthwise conv (k=4) + SiLU, relayout to head-major ----
__global__ void conv_silu_kernel(const float* __restrict__ qp, const float* __restrict__ kp,
                                 const float* __restrict__ vp,
                                 const float* __restrict__ wq, const float* __restrict__ wk,
                                 const float* __restrict__ wv,
                                 float* __restrict__ qo, float* __restrict__ ko,
                                 float* __restrict__ vo)
{
    const int row = blockIdx.x;                 // b*L + l
    const int d   = blockIdx.y*256 + threadIdx.x;
    const int l = row & (Lq-1), b = row >> 12;
    const int h = d >> 8, dk = d & 255;
    float aq=0.f, ak=0.f, av=0.f;
    #pragma unroll
    for (int j=0;j<4;j++){
        int ls = l - 3 + j;
        if (ls >= 0){
            size_t idx = (size_t)(row - 3 + j)*Dq + d;
            aq = fmaf(qp[idx], wq[d*4+j], aq);
            ak = fmaf(kp[idx], wk[d*4+j], ak);
            av = fmaf(vp[idx], wv[d*4+j], av);
        }
    }
    size_t o = ((size_t)(b*Hq + h)*Lq + l)*256 + dk;
    qo[o] = silu(aq);
    ko[o] = silu(ak);
    vo[o] = silu(av);
}

// ---------------- beta / g_s / g_l projections ----------------
__global__ void smallproj_kernel(const float* __restrict__ x,
                                 const float* __restrict__ Wb, const float* __restrict__ Wds,
                                 const float* __restrict__ bds, const float* __restrict__ Wdl,
                                 const float* __restrict__ bdl,
                                 float* __restrict__ beta, float* __restrict__ gs,
                                 float* __restrict__ gl)
{
    const int row = blockIdx.x;
    const float* xr = x + (size_t)row*Dq;
    float acc[12];
    #pragma unroll
    for (int r=0;r<12;r++) acc[r]=0.f;
    for (int j=threadIdx.x;j<Dq;j+=256){
        const float xv = xr[j];
        #pragma unroll
        for (int h=0;h<4;h++){
            acc[h]   = fmaf(xv, Wb [h*Dq+j], acc[h]);
            acc[4+h] = fmaf(xv, Wds[h*Dq+j], acc[4+h]);
            acc[8+h] = fmaf(xv, Wdl[h*Dq+j], acc[8+h]);
        }
    }
    __shared__ float red[12][9];
    const int lane = threadIdx.x & 31, w = threadIdx.x >> 5;
    #pragma unroll
    for (int r=0;r<12;r++){
        float s = warp_sum(acc[r]);
        if (lane==0) red[r][w] = s;
    }
    __syncthreads();
    if (threadIdx.x < 12){
        float s = 0.f;
        #pragma unroll
        for (int ww=0;ww<8;ww++) s += red[threadIdx.x][ww];
        const int h = threadIdx.x & 3;
        const int b = row >> 12, l = row & (Lq-1);
        size_t o = (size_t)(b*4 + h)*Lq + l;
        if (threadIdx.x < 4)      beta[o] = sigm(s);
        else if (threadIdx.x < 8) gs[o]   = sigm(s + bds[h]);
        else                      gl[o]   = sigm(s + bdl[h]);
    }
}

// ---------------- delta-rule per-chunk precompute ----------------
__global__ void chunk_pre_kernel(float* __restrict__ q, float* __restrict__ k,
                                 const float* __restrict__ v, const float* __restrict__ beta,
                                 float* __restrict__ u, float* __restrict__ w,
                                 float* __restrict__ attn)
{
    extern __shared__ float sm[];
    float* qs = sm;              // 32*257
    float* ks = qs + 8224;
    float* vs = ks + 8224;
    float* Lm = vs + 8224;       // 32*33
    float* Ti = Lm + 1056;       // 32*33
    float* bs = Ti + 1056;       // 32
    const int bh = blockIdx.x >> 7;
    const int c  = blockIdx.x & 127;
    const int tid = threadIdx.x, lane = tid&31, wid = tid>>5;
    const size_t base = (size_t)bh*Lq + (size_t)c*CHK;

    for (int idx = tid; idx < 32*256; idx += 256){
        int i = idx >> 8, d = idx & 255;
        size_t g = (base + i)*256 + d;
        qs[i*257+d] = q[g];
        ks[i*257+d] = k[g];
        vs[i*257+d] = v[g];
    }
    if (tid < 32) bs[tid] = beta[base + tid];
    __syncthreads();

    #pragma unroll
    for (int r=0;r<4;r++){
        int i = wid*4 + r;
        float sq=0.f, sk=0.f;
        for (int d=lane; d<256; d+=32){
            float a=qs[i*257+d]; sq=fmaf(a,a,sq);
            float bb=ks[i*257+d]; sk=fmaf(bb,bb,sk);
        }
        sq = warp_sum(sq); sk = warp_sum(sk);
        float rq = rsqrtf(sq + 1e-6f), rk = rsqrtf(sk + 1e-6f);
        for (int d=lane; d<256; d+=32){ qs[i*257+d]*=rq; ks[i*257+d]*=rk; }
    }
    __syncthreads();

    for (int idx = tid; idx < 32*256; idx += 256){
        int i = idx>>8, d = idx&255;
        size_t g = (base+i)*256 + d;
        q[g] = qs[i*257+d];
        k[g] = ks[i*257+d];
        vs[i*257+d] *= bs[i];
    }
    __syncthreads();

    #pragma unroll
    for (int r=0;r<4;r++){
        int i = wid + 8*r;
        float aq=0.f, akk=0.f;
        for (int d=0; d<256; d++){
            float kjd = ks[lane*257+d];
            aq  = fmaf(qs[i*257+d], kjd, aq);
            akk = fmaf(ks[i*257+d], kjd, akk);
        }
        Lm[i*33+lane] = (lane < i) ? bs[i]*akk : 0.f;
        attn[(size_t)blockIdx.x*1024 + i*32 + lane] = (lane <= i) ? aq : 0.f;
    }
    __syncthreads();

    if (wid == 0){
        for (int i=0;i<32;i++){
            float xv = (lane==i) ? 1.f : 0.f;
            for (int p=0;p<i;p++) xv = fmaf(-Lm[i*33+p], Ti[p*33+lane], xv);
            Ti[i*33+lane] = xv;
            __syncwarp();
        }
    }
    __syncthreads();

    for (int idx = tid; idx < 1024; idx += 256){
        int i = idx>>5, j = idx&31;
        Lm[i*33+j] = Ti[i*33+j]*bs[j];
    }
    __syncthreads();

    #pragma unroll
    for (int r=0;r<4;r++){
        int i = wid + 8*r;
        #pragma unroll
        for (int m=0;m<8;m++){
            int d = lane + 32*m;
            float au=0.f, aw=0.f;
            #pragma unroll
            for (int j=0;j<32;j++){
                au = fmaf(Ti[i*33+j], vs[j*257+d], au);
                aw = fmaf(Lm[i*33+j], ks[j*257+d], aw);
            }
            size_t g = (base+i)*256 + d;
            u[g] = au;
            w[g] = aw;
        }
    }
}

// ---------------- delta-rule inter-chunk scan (TF32 wmma, split-precision S) ----
// grid: 16 (b,h) * 8 dv-slices of 32; 256 threads (8 warps).
__global__ void scan_kernel(const float* __restrict__ q, const float* __restrict__ k,
                            const float* __restrict__ u, const float* __restrict__ w,
                            const float* __restrict__ attn, float* __restrict__ o)
{
    extern __shared__ float sm[];
    float* S   = sm;                  // 256*36 fp32 master
    float* Shi = S   + 256*SLD;       // tf32-exact high part
    float* Slo = Shi + 256*SLD;       // tf32 residual
    float* uh  = Slo + 256*SLD;       // 32*36 fp32
    float* uhh = uh  + 32*SLD;
    float* uhl = uhh + 32*SLD;
    const int bh = blockIdx.x >> 3;
    const int d0 = (blockIdx.x & 7) * 32;
    const int tid = threadIdx.x, warp = tid >> 5;

    for (int i = tid; i < 3*256*SLD; i += 256) sm[i] = 0.f;
    __syncthreads();

    wmma::fragment<wmma::accumulator,16,16,8,float> acc2;  // warps 4-7: q@S then +attn@uh

    for (int c = 0; c < NCHK; ++c){
        const size_t base = (size_t)bh*Lq + (size_t)c*32;
        const float* qg = q + base*256;
        const float* kg = k + base*256;
        const float* wg = w + base*256;
        const float* ug = u + base*256 + d0;
        const float* ag = attn + ((size_t)bh*NCHK + c)*1024;
        float*       og = o + base*256 + d0;

        // split S -> Shi (13-bit truncation, exactly tf32) + Slo (tf32 residual)
        for (int idx = tid; idx < 256*32; idx += 256){
            int r = idx >> 5, cc = idx & 31;
            float s = S[r*SLD + cc];
            float hi = __uint_as_float(__float_as_uint(s) & 0xFFFFE000u);
            Shi[r*SLD + cc] = hi;
            Slo[r*SLD + cc] = wmma::__float_to_tf32(s - hi);
        }
        __syncthreads();

        if (warp < 4){
            // uh = u - w @ (Shi + Slo) ; one 16x16 tile per warp
            const int i0 = (warp & 1)*16, j0 = (warp >> 1)*16;
            wmma::fragment<wmma::accumulator,16,16,8,float> acc;
            wmma::load_matrix_sync(acc, ug + (size_t)i0*256 + j0, 256, wmma::mem_row_major);
            #pragma unroll 4
            for (int dk0 = 0; dk0 < 256; dk0 += 8){
                wmma::fragment<wmma::matrix_a,16,16,8,wmma::precision::tf32,wmma::row_major> af;
                wmma::load_matrix_sync(af, wg + (size_t)i0*256 + dk0, 256);
                #pragma unroll
                for (int t=0;t<af.num_elements;t++) af.x[t] = wmma::__float_to_tf32(-af.x[t]);
                wmma::fragment<wmma::matrix_b,16,16,8,wmma::precision::tf32,wmma::row_major> bf;
                wmma::load_matrix_sync(bf, Shi + dk0*SLD + j0, SLD);
                wmma::mma_sync(acc, af, bf, acc);
                wmma::load_matrix_sync(bf, Slo + dk0*SLD + j0, SLD);
                wmma::mma_sync(acc, af, bf, acc);
            }
            wmma::store_matrix_sync(uh + i0*SLD + j0, acc, SLD, wmma::mem_row_major);
        } else {
            // q @ (Shi + Slo) partial kept in registers
            const int i0 = ((warp-4) & 1)*16, j0 = ((warp-4) >> 1)*16;
            wmma::fill_fragment(acc2, 0.f);
            #pragma unroll 4
            for (int dk0 = 0; dk0 < 256; dk0 += 8){
                wmma::fragment<wmma::matrix_a,16,16,8,wmma::precision::tf32,wmma::row_major> af;
                wmma::load_matrix_sync(af, qg + (size_t)i0*256 + dk0, 256);
                #pragma unroll
                for (int t=0;t<af.num_elements;t++) af.x[t] = wmma::__float_to_tf32(af.x[t]);
                wmma::fragment<wmma::matrix_b,16,16,8,wmma::precision::tf32,wmma::row_major> bf;
                wmma::load_matrix_sync(bf, Shi + dk0*SLD + j0, SLD);
                wmma::mma_sync(acc2, af, bf, acc2);
                wmma::load_matrix_sync(bf, Slo + dk0*SLD + j0, SLD);
                wmma::mma_sync(acc2, af, bf, acc2);
            }
        }
        __syncthreads();

        // split uh -> uhh + uhl
        for (int idx = tid; idx < 1024; idx += 256){
            int r = idx >> 5, cc = idx & 31;
            float s = uh[r*SLD + cc];
            float hi = __uint_as_float(__float_as_uint(s) & 0xFFFFE000u);
            uhh[r*SLD + cc] = hi;
            uhl[r*SLD + cc] = wmma::__float_to_tf32(s - hi);
        }
        __syncthreads();

        if (warp < 4){
            // S += k^T @ (uhh + uhl) ; 8 tiles (16 dk x 16 dv) per warp
            #pragma unroll
            for (int t = 0; t < 8; t++){
                const int id = warp*8 + t;
                const int dk0 = (id >> 1)*16, j0 = (id & 1)*16;
                wmma::fragment<wmma::accumulator,16,16,8,float> acc;
                wmma::load_matrix_sync(acc, S + dk0*SLD + j0, SLD, wmma::mem_row_major);
                #pragma unroll
                for (int i2 = 0; i2 < 32; i2 += 8){
                    wmma::fragment<wmma::matrix_a,16,16,8,wmma::precision::tf32,wmma::col_major> af;
                    wmma::load_matrix_sync(af, kg + (size_t)i2*256 + dk0, 256);
                    #pragma unroll
                    for (int tt=0;tt<af.num_elements;tt++) af.x[tt] = wmma::__float_to_tf32(af.x[tt]);
                    wmma::fragment<wmma::matrix_b,16,16,8,wmma::precision::tf32,wmma::row_major> bf;
                    wmma::load_matrix_sync(bf, uhh + i2*SLD + j0, SLD);
                    wmma::mma_sync(acc, af, bf, acc);
                    wmma::load_matrix_sync(bf, uhl + i2*SLD + j0, SLD);
                    wmma::mma_sync(acc, af, bf, acc);
                }
                wmma::store_matrix_sync(S + dk0*SLD + j0, acc, SLD, wmma::mem_row_major);
            }
        } else {
            // o = q@S + attn @ (uhh + uhl)
            const int i0 = ((warp-4) & 1)*16, j0 = ((warp-4) >> 1)*16;
            #pragma unroll
            for (int i2 = 0; i2 < 32; i2 += 8){
                wmma::fragment<wmma::matrix_a,16,16,8,wmma::precision::tf32,wmma::row_major> af;
                wmma::load_matrix_sync(af, ag + i0*32 + i2, 32);
                #pragma unroll
                for (int tt=0;tt<af.num_elements;tt++) af.x[tt] = wmma::__float_to_tf32(af.x[tt]);
                wmma::fragment<wmma::matrix_b,16,16,8,wmma::precision::tf32,wmma::row_major> bf;
                wmma::load_matrix_sync(bf, uhh + i2*SLD + j0, SLD);
                wmma::mma_sync(acc2, af, bf, acc2);
                wmma::load_matrix_sync(bf, uhl + i2*SLD + j0, SLD);
                wmma::mma_sync(acc2, af, bf, acc2);
            }
            wmma::store_matrix_sync(og + (size_t)i0*256 + j0, acc2, 256, wmma::mem_row_major);
        }
        __syncthreads();
    }
}

// ---------------- dual EMA (128 blocks x 32 threads) ----------------
__global__ void ema_kernel(const float* __restrict__ v, const float* __restrict__ gs,
                           const float* __restrict__ gl,
                           float* __restrict__ es, float* __restrict__ el)
{
    const int bh = blockIdx.x >> 3;
    const int dv = ((blockIdx.x & 7) << 5) + threadIdx.x;
    const size_t vbase = (size_t)bh*Lq*256 + dv;
    const float* gsp = gs + (size_t)bh*Lq;
    const float* glp = gl + (size_t)bh*Lq;
    float ss = 0.f, sl = 0.f;
    #pragma unroll 8
    for (int t=0;t<Lq;t++){
        float vv = v[vbase + (size_t)t*256];
        float a = gsp[t], b2 = glp[t];
        ss = fmaf(a, ss, (1.f-a)*vv);
        sl = fmaf(b2, sl, (1.f-b2)*vv);
        es[vbase + (size_t)t*256] = ss;
        el[vbase + (size_t)t*256] = sl;
    }
}

// ---------------- hierarchical gate heads ----------------
__global__ void gate_head_kernel(const float* __restrict__ z,
                                 const float* __restrict__ Wc, const float* __restrict__ bc,
                                 const float* __restrict__ Wl, const float* __restrict__ bl,
                                 const float* __restrict__ Wg, const float* __restrict__ bg,
                                 const float* __restrict__ ltc, const float* __restrict__ ltf,
                                 float* __restrict__ wgt)
{
    const int row = blockIdx.x;
    const float* zr = z + (size_t)row*512;
    float acc[24];
    #pragma unroll
    for (int r=0;r<24;r++) acc[r]=0.f;
    for (int j=threadIdx.x;j<512;j+=256){
        float zv = zr[j];
        #pragma unroll
        for (int r=0;r<8;r++){
            acc[r]    = fmaf(zv, Wc[r*512+j], acc[r]);
            acc[8+r]  = fmaf(zv, Wl[r*512+j], acc[8+r]);
            acc[16+r] = fmaf(zv, Wg[r*512+j], acc[16+r]);
        }
    }
    __shared__ float red[24][9];
    const int lane = threadIdx.x&31, w = threadIdx.x>>5;
    #pragma unroll
    for (int r=0;r<24;r++){
        float s = warp_sum(acc[r]);
        if (lane==0) red[r][w] = s;
    }
    __syncthreads();
    if (threadIdx.x < 4){
        const int h = threadIdx.x;
        float sums[6];
        int rs[6] = {2*h, 2*h+1, 8+2*h, 8+2*h+1, 16+2*h, 16+2*h+1};
        #pragma unroll
        for (int t=0;t<6;t++){
            float s=0.f;
            #pragma unroll
            for (int ww=0;ww<8;ww++) s += red[rs[t]][ww];
            sums[t]=s;
        }
        float tc = log1pf(expf(ltc[h])) + 1e-4f;
        float tf = log1pf(expf(ltf[h])) + 1e-4f;
        float c0 = sums[0]+bc[2*h], c1 = sums[1]+bc[2*h+1];
        float l0 = sums[2]+bl[2*h], l1 = sums[3]+bl[2*h+1];
        float g0 = sums[4]+bg[2*h], g1 = sums[5]+bg[2*h+1];
        float pg0 = sigm((c0-c1)/tc), pg1 = 1.f - pg0;
        float q0  = sigm((l0-l1)/tf), q1 = 1.f - q0;
        float r0  = sigm((g0-g1)/tf), r1 = 1.f - r0;
        size_t o = (size_t)row*16 + h*4;
        wgt[o+0] = pg0*q0; wgt[o+1] = pg0*q1; wgt[o+2] = pg1*r0; wgt[o+3] = pg1*r1;
    }
}

// ---------------- mix + per-head RMSNorm ----------------
__global__ void combine_kernel(const float* __restrict__ v, const float* __restrict__ es,
                               const float* __restrict__ el, const float* __restrict__ dl,
                               const float* __restrict__ wgt, const float* __restrict__ onw,
                               float* __restrict__ omix)
{
    const int blk = blockIdx.x;           // row*4 + h
    const int row = blk >> 2, h = blk & 3;
    const int b = row >> 12, l = row & (Lq-1);
    const int tid = threadIdx.x;
    const size_t gbase = ((size_t)(b*4+h)*Lq + l)*256 + tid;
    const float* wp = wgt + (size_t)row*16 + h*4;
    float w0 = wp[0], w1 = wp[1], w2 = wp[2], w3 = wp[3];
    float val = w0*v[gbase] + w1*es[gbase] + w2*dl[gbase] + w3*el[gbase];

    float s = warp_sum(val*val);
    __shared__ float red[8];
    const int lane = tid&31, w = tid>>5;
    if (lane==0) red[w] = s;
    __syncthreads();
    if (w==0){
        float t = (lane<8)?red[lane]:0.f;
        t = warp_sum(t);
        if (lane==0) red[0] = t;
    }
    __syncthreads();
    float rms = rsqrtf(red[0]*(1.f/256.f) + 1e-5f);
    omix[(size_t)row*1024 + h*256 + tid] = val*rms*onw[tid];
}

// ---------------- host ----------------
extern "C" void kernel_launch(void* const* d_in, const int* in_sizes, int n_in,
                              void* d_out, int out_size)
{
    const float* x      = (const float*)d_in[0];
    const float* Wq     = (const float*)d_in[1];
    const float* Wk     = (const float*)d_in[2];
    const float* Wv     = (const float*)d_in[3];
    const float* cqw    = (const float*)d_in[4];
    const float* ckw    = (const float*)d_in[5];
    const float* cvw    = (const float*)d_in[6];
    const float* Wb     = (const float*)d_in[7];
    const float* Wds    = (const float*)d_in[8];
    const float* bds    = (const float*)d_in[9];
    const float* Wdl    = (const float*)d_in[10];
    const float* bdl    = (const float*)d_in[11];
    const float* Wtrunk = (const float*)d_in[12];
    const float* btrunk = (const float*)d_in[13];
    const float* Wcoarse= (const float*)d_in[14];
    const float* bcoarse= (const float*)d_in[15];
    const float* Wlocal = (const float*)d_in[16];
    const float* blocal = (const float*)d_in[17];
    const float* Wglobal= (const float*)d_in[18];
    const float* bglobal= (const float*)d_in[19];
    const float* ltc    = (const float*)d_in[20];
    const float* ltf    = (const float*)d_in[21];
    const float* onw    = (const float*)d_in[22];
    const float* Wo     = (const float*)d_in[23];
    float* out = (float*)d_out;

    float* arena;
    cudaGetSymbolAddress((void**)&arena, g_arena);
    float* qpre = arena + OFF_QPRE;
    float* kpre = arena + OFF_KPRE;
    float* vpre = arena + OFF_VPRE;
    float* qb   = arena + OFF_Q;
    float* kb   = arena + OFF_K;
    float* vb   = arena + OFF_V;
    float* ub   = arena + OFF_U;
    float* wb   = arena + OFF_W;
    float* dlt  = arena + OFF_DELTA;
    float* emas = arena + OFF_EMAS;
    float* emal = arena + OFF_EMAL;
    float* omix = arena + OFF_OMIX;
    float* zb   = arena + OFF_Z;
    float* attn = arena + OFF_ATTN;
    float* beta = arena + OFF_BETA;
    float* gs   = arena + OFF_GS;
    float* gl   = arena + OFF_GL;
    float* wgt  = arena + OFF_WGT;

    cudaFuncSetAttribute(gemm_tf32_kernel, cudaFuncAttributeMaxDynamicSharedMemorySize, GEMM_SMEM_BYTES);
    cudaFuncSetAttribute(chunk_pre_kernel, cudaFuncAttributeMaxDynamicSharedMemorySize, PRE_SMEM_BYTES);
    cudaFuncSetAttribute(scan_kernel,      cudaFuncAttributeMaxDynamicSharedMemorySize, SCAN_SMEM_BYTES);

    dim3 blk(256);
    dim3 gN(1024/GBN, MROWS/GBM);
    dim3 gZ(512/GBN,  MROWS/GBM);

    // projections (TF32 tensor cores, double-buffered)
    gemm_tf32_kernel<<<gN, blk, GEMM_SMEM_BYTES>>>(x, Wq, nullptr, qpre, MROWS, 1024, 1024, 0);
    gemm_tf32_kernel<<<gN, blk, GEMM_SMEM_BYTES>>>(x, Wk, nullptr, kpre, MROWS, 1024, 1024, 0);
    gemm_tf32_kernel<<<gN, blk, GEMM_SMEM_BYTES>>>(x, Wv, nullptr, vpre, MROWS, 1024, 1024, 0);

    // conv + silu + relayout
    conv_silu_kernel<<<dim3(MROWS,4), blk>>>(qpre, kpre, vpre, cqw, ckw, cvw, qb, kb, vb);

    // beta / decays
    smallproj_kernel<<<MROWS, blk>>>(x, Wb, Wds, bds, Wdl, bdl, beta, gs, gl);

    // delta rule
    chunk_pre_kernel<<<2048, blk, PRE_SMEM_BYTES>>>(qb, kb, vb, beta, ub, wb, attn);
    scan_kernel<<<128, blk, SCAN_SMEM_BYTES>>>(qb, kb, ub, wb, attn, dlt);

    // EMAs
    ema_kernel<<<128, 32>>>(vb, gs, gl, emas, emal);

    // gate
    gemm_tf32_kernel<<<gZ, blk, GEMM_SMEM_BYTES>>>(x, Wtrunk, btrunk, zb, MROWS, 512, 1024, 1);
    gate_head_kernel<<<MROWS, blk>>>(zb, Wcoarse, bcoarse, Wlocal, blocal,
                                     Wglobal, bglobal, ltc, ltf, wgt);

    // combine + RMSNorm
    combine_kernel<<<MROWS*4, blk>>>(vb, emas, emal, dlt, wgt, onw, omix);

    // output projection
    gemm_tf32_kernel<<<gN, blk, GEMM_SMEM_BYTES>>>(omix, Wo, nullptr, out, MROWS, 1024, 1024, 0);
}